// round 3
// baseline (speedup 1.0000x reference)
#include <cuda_runtime.h>
#include <math.h>

#define N_FIELDS 8
#define HIDDEN   128
#define GEO      15
#define APP      32
#define CIN      50     // 3 dir + 15 geo + 32 app
#define CINP     56     // padded: 28 f32 pairs, 224B rows (16B aligned)
#define N_MAX    524288
#define TILE     128

typedef unsigned long long u64;

// ---------------- packed f32x2 helpers (Blackwell FFMA2) --------------------
__device__ __forceinline__ void fma2(u64& d, u64 a, u64 b, u64 c) {
    asm("fma.rn.f32x2 %0, %1, %2, %3;" : "=l"(d) : "l"(a), "l"(b), "l"(c));
}
__device__ __forceinline__ u64 pk2(float lo, float hi) {
    u64 r;
    asm("mov.b64 %0, {%1, %2};"
        : "=l"(r) : "r"(__float_as_uint(lo)), "r"(__float_as_uint(hi)));
    return r;
}
__device__ __forceinline__ float2 up2(u64 v) {
    unsigned lo, hi;
    asm("mov.b64 {%0, %1}, %2;" : "=r"(lo), "=r"(hi) : "l"(v));
    return make_float2(__uint_as_float(lo), __uint_as_float(hi));
}

// ---------------- device scratch (static globals, no allocation) -----------
__device__ int g_counts[N_FIELDS];
__device__ int g_bucket[N_FIELDS][N_MAX];

// ---------------- kernel 0: zero counters ----------------------------------
__global__ void k_zero() {
    if (threadIdx.x < N_FIELDS) g_counts[threadIdx.x] = 0;
}

// ---------------- kernel 1: assign + warp-aggregated scatter ---------------
__global__ void k_assign(const float* __restrict__ pos,
                         const float* __restrict__ cent, int n) {
    int i = blockIdx.x * blockDim.x + threadIdx.x;
    unsigned act = __ballot_sync(0xffffffffu, i < n);
    if (i >= n) return;

    float px = pos[3*i], py = pos[3*i+1], pz = pos[3*i+2];
    int best = 0; float bd = 3.402823e38f;
    #pragma unroll
    for (int c = 0; c < N_FIELDS; c++) {
        float dx = px - __ldg(&cent[3*c+0]);
        float dy = py - __ldg(&cent[3*c+1]);
        float dz = pz - __ldg(&cent[3*c+2]);
        float d = dx*dx + dy*dy + dz*dz;
        if (d < bd) { bd = d; best = c; }   // strict < => first min wins
    }

    unsigned peers  = __match_any_sync(act, best);
    int      leader = __ffs(peers) - 1;
    int      lane   = threadIdx.x & 31;
    int base = 0;
    if (lane == leader) base = atomicAdd(&g_counts[best], __popc(peers));
    base = __shfl_sync(peers, base, leader);
    int slot = base + __popc(peers & ((1u << lane) - 1u));
    g_bucket[best][slot] = i;
}

// ---------------- kernel 2: per-field dense MLP (packed f32x2) -------------
__global__ void __launch_bounds__(TILE)
k_field(const float* __restrict__ pos, const float* __restrict__ dir,
        const float* __restrict__ app,
        const float* __restrict__ Wd1, const float* __restrict__ bd1,
        const float* __restrict__ Wd2, const float* __restrict__ bd2,
        const float* __restrict__ Wc1, const float* __restrict__ bc1,
        const float* __restrict__ Wc2, const float* __restrict__ bc2,
        float* __restrict__ out, int tpf)
{
    __shared__ __align__(16) float sWd1[3*HIDDEN];
    __shared__ __align__(16) float sbd1[HIDDEN];
    __shared__ __align__(16) float sWd2[HIDDEN*16];
    __shared__ __align__(16) float sbd2[16];
    __shared__ __align__(16) float sWc1[HIDDEN*CINP];   // transposed [j][k], k padded to 56
    __shared__ __align__(16) float sbc1[HIDDEN];
    __shared__ __align__(16) float sWc2c[3][HIDDEN];    // component-major
    __shared__ __align__(16) float sbc2[4];

    int f = blockIdx.x / tpf;
    int t = blockIdx.x - f * tpf;
    int cnt = g_counts[f];
    if (t * TILE >= cnt) return;

    int tid = threadIdx.x;

    // ---- stage weights into smem ----
    {
        const float* g = Wd1 + f*3*HIDDEN;
        for (int i = tid; i < 3*HIDDEN; i += TILE) sWd1[i] = g[i];
    }
    sbd1[tid] = bd1[f*HIDDEN + tid];
    {
        const float* g = Wd2 + f*HIDDEN*16;
        for (int i = tid; i < HIDDEN*16; i += TILE) sWd2[i] = g[i];
    }
    if (tid < 16) sbd2[tid] = bd2[f*16 + tid];
    {   // transpose Wc1 [k][j] -> sWc1 [j][k]
        const float* g = Wc1 + f*CIN*HIDDEN;
        for (int i = tid; i < CIN*HIDDEN; i += TILE) {
            int k = i / HIDDEN, j = i - k*HIDDEN;
            sWc1[j*CINP + k] = g[i];
        }
        #pragma unroll
        for (int c = CIN; c < CINP; c++) sWc1[tid*CINP + c] = 0.f;  // tid spans all j
    }
    sbc1[tid] = bc1[f*HIDDEN + tid];
    {
        const float* g = Wc2 + f*HIDDEN*3;
        sWc2c[0][tid] = g[tid*3+0];
        sWc2c[1][tid] = g[tid*3+1];
        sWc2c[2][tid] = g[tid*3+2];
    }
    if (tid < 3) sbc2[tid] = bc2[f*3 + tid];
    if (tid == 3) sbc2[3] = 0.f;
    __syncthreads();

    int bi = t * TILE + tid;
    if (bi >= cnt) return;
    int p = g_bucket[f][bi];

    float px = pos[3*p], py = pos[3*p+1], pz = pos[3*p+2];
    u64 px2 = pk2(px, px), py2 = pk2(py, py), pz2 = pk2(pz, pz);

    // ---- layer 1: h = relu(pos @ Wd1 + bd1) ----
    float h[HIDDEN];
    #pragma unroll
    for (int j = 0; j < HIDDEN; j += 4) {
        ulonglong2 w0 = *(const ulonglong2*)&sWd1[0*HIDDEN + j];
        ulonglong2 w1 = *(const ulonglong2*)&sWd1[1*HIDDEN + j];
        ulonglong2 w2 = *(const ulonglong2*)&sWd1[2*HIDDEN + j];
        ulonglong2 b  = *(const ulonglong2*)&sbd1[j];
        u64 a0 = b.x, a1 = b.y;
        fma2(a0, px2, w0.x, a0);  fma2(a1, px2, w0.y, a1);
        fma2(a0, py2, w1.x, a0);  fma2(a1, py2, w1.y, a1);
        fma2(a0, pz2, w2.x, a0);  fma2(a1, pz2, w2.y, a1);
        float2 f0 = up2(a0), f1 = up2(a1);
        h[j+0] = fmaxf(f0.x, 0.f);  h[j+1] = fmaxf(f0.y, 0.f);
        h[j+2] = fmaxf(f1.x, 0.f);  h[j+3] = fmaxf(f1.y, 0.f);
    }

    // ---- layer 2: dout = h @ Wd2 + bd2 (8 packed accumulators) ----
    u64 d2[8];
    #pragma unroll
    for (int q = 0; q < 8; q++) d2[q] = *(const u64*)&sbd2[2*q];
    #pragma unroll
    for (int k = 0; k < HIDDEN; k++) {
        u64 hk2 = pk2(h[k], h[k]);
        const ulonglong2* wr = (const ulonglong2*)&sWd2[k*16];
        #pragma unroll
        for (int q = 0; q < 4; q++) {
            ulonglong2 w = wr[q];
            fma2(d2[2*q+0], hk2, w.x, d2[2*q+0]);
            fma2(d2[2*q+1], hk2, w.y, d2[2*q+1]);
        }
    }
    float d0[16];
    #pragma unroll
    for (int q = 0; q < 8; q++) {
        float2 v = up2(d2[q]);
        d0[2*q+0] = v.x;  d0[2*q+1] = v.y;
    }
    float density = expf(d0[0]);

    // ---- build packed cin = [dir, geo, app, pad] (28 f32 pairs) ----
    float cin[CINP];
    cin[0] = dir[3*p]; cin[1] = dir[3*p+1]; cin[2] = dir[3*p+2];
    #pragma unroll
    for (int g = 0; g < GEO; g++) cin[3+g] = d0[1+g];
    {
        const float4* ap = (const float4*)(app + (size_t)p*APP);
        #pragma unroll
        for (int q = 0; q < APP/4; q++) {
            float4 v = __ldg(&ap[q]);
            cin[18+4*q+0] = v.x; cin[18+4*q+1] = v.y;
            cin[18+4*q+2] = v.z; cin[18+4*q+3] = v.w;
        }
    }
    #pragma unroll
    for (int c = CIN; c < CINP; c++) cin[c] = 0.f;
    u64 cin2[CINP/2];
    #pragma unroll
    for (int q = 0; q < CINP/2; q++) cin2[q] = pk2(cin[2*q], cin[2*q+1]);

    // ---- color MLP: two hidden units per iteration, packed throughout ----
    // Each weight row = 56 floats = 28 u64 pairs = 14 ulonglong2 (FIXED bound)
    u64 rp0 = 0ull, rp1 = 0ull, rp2 = 0ull;
    for (int j = 0; j < HIDDEN; j += 2) {
        const ulonglong2* wa = (const ulonglong2*)&sWc1[(j+0)*CINP];
        const ulonglong2* wb = (const ulonglong2*)&sWc1[(j+1)*CINP];
        u64 aA0 = 0ull, aA1 = 0ull, aB0 = 0ull, aB1 = 0ull;
        #pragma unroll
        for (int q = 0; q < CINP/4; q++) {            // 14 ulonglong2 per row
            ulonglong2 wA = wa[q];
            ulonglong2 wB = wb[q];
            fma2(aA0, cin2[2*q+0], wA.x, aA0);
            fma2(aA1, cin2[2*q+1], wA.y, aA1);
            fma2(aB0, cin2[2*q+0], wB.x, aB0);
            fma2(aB1, cin2[2*q+1], wB.y, aB1);
        }
        float2 vA0 = up2(aA0), vA1 = up2(aA1);
        float2 vB0 = up2(aB0), vB1 = up2(aB1);
        float hcA = fmaxf((vA0.x + vA0.y) + (vA1.x + vA1.y) + sbc1[j+0], 0.f);
        float hcB = fmaxf((vB0.x + vB0.y) + (vB1.x + vB1.y) + sbc1[j+1], 0.f);
        u64 hc2 = pk2(hcA, hcB);
        fma2(rp0, hc2, *(const u64*)&sWc2c[0][j], rp0);
        fma2(rp1, hc2, *(const u64*)&sWc2c[1][j], rp1);
        fma2(rp2, hc2, *(const u64*)&sWc2c[2][j], rp2);
    }
    float2 v0 = up2(rp0), v1 = up2(rp1), v2 = up2(rp2);
    float r0 = v0.x + v0.y + sbc2[0];
    float r1 = v1.x + v1.y + sbc2[1];
    float r2 = v2.x + v2.y + sbc2[2];

    float4 o;
    o.x = density;
    o.y = 1.f / (1.f + expf(-r0));
    o.z = 1.f / (1.f + expf(-r1));
    o.w = 1.f / (1.f + expf(-r2));
    *(float4*)&out[(size_t)4*p] = o;
}

// ---------------- launch ----------------------------------------------------
extern "C" void kernel_launch(void* const* d_in, const int* in_sizes, int n_in,
                              void* d_out, int out_size) {
    const float* positions  = (const float*)d_in[0];
    const float* directions = (const float*)d_in[1];
    const float* appearance = (const float*)d_in[2];
    const float* centroids  = (const float*)d_in[3];
    const float* Wd1 = (const float*)d_in[4];
    const float* bd1 = (const float*)d_in[5];
    const float* Wd2 = (const float*)d_in[6];
    const float* bd2 = (const float*)d_in[7];
    const float* Wc1 = (const float*)d_in[8];
    const float* bc1 = (const float*)d_in[9];
    const float* Wc2 = (const float*)d_in[10];
    const float* bc2 = (const float*)d_in[11];
    float* out = (float*)d_out;

    int n = in_sizes[0] / 3;
    if (n > N_MAX) n = N_MAX;

    int tpf = (n + TILE - 1) / TILE;

    k_zero<<<1, 32>>>();
    k_assign<<<(n + 255) / 256, 256>>>(positions, centroids, n);
    k_field<<<N_FIELDS * tpf, TILE>>>(positions, directions, appearance,
                                      Wd1, bd1, Wd2, bd2, Wc1, bc1, Wc2, bc2,
                                      out, tpf);
}

// round 4
// speedup vs baseline: 1.2080x; 1.2080x over previous
#include <cuda_runtime.h>
#include <math.h>

#define N_FIELDS 8
#define HIDDEN   128
#define GEO      15
#define APP      32
#define CIN      50     // 3 dir + 15 geo + 32 app
#define CINP     52     // padded to multiple of 4
#define N_MAX    524288
#define TILE     128

// ---------------- device scratch (static globals, no allocation) -----------
__device__ int g_counts[N_FIELDS];
__device__ int g_bucket[N_FIELDS][N_MAX];

// ---------------- kernel 0: zero counters ----------------------------------
__global__ void k_zero() {
    if (threadIdx.x < N_FIELDS) g_counts[threadIdx.x] = 0;
}

// ---------------- kernel 1: assign + warp-aggregated scatter ---------------
__global__ void k_assign(const float* __restrict__ pos,
                         const float* __restrict__ cent, int n) {
    int i = blockIdx.x * blockDim.x + threadIdx.x;
    unsigned act = __ballot_sync(0xffffffffu, i < n);
    if (i >= n) return;

    float px = pos[3*i], py = pos[3*i+1], pz = pos[3*i+2];
    int best = 0; float bd = 3.402823e38f;
    #pragma unroll
    for (int c = 0; c < N_FIELDS; c++) {
        float dx = px - __ldg(&cent[3*c+0]);
        float dy = py - __ldg(&cent[3*c+1]);
        float dz = pz - __ldg(&cent[3*c+2]);
        float d = dx*dx + dy*dy + dz*dz;
        if (d < bd) { bd = d; best = c; }   // strict < => first min wins
    }

    unsigned peers  = __match_any_sync(act, best);
    int      leader = __ffs(peers) - 1;
    int      lane   = threadIdx.x & 31;
    int base = 0;
    if (lane == leader) base = atomicAdd(&g_counts[best], __popc(peers));
    base = __shfl_sync(peers, base, leader);
    int slot = base + __popc(peers & ((1u << lane) - 1u));
    g_bucket[best][slot] = i;
}

// ---------------- kernel 2: per-field dense MLP (fused L1+L2) --------------
__global__ void __launch_bounds__(TILE, 4)
k_field(const float* __restrict__ pos, const float* __restrict__ dir,
        const float* __restrict__ app,
        const float* __restrict__ Wd1, const float* __restrict__ bd1,
        const float* __restrict__ Wd2, const float* __restrict__ bd2,
        const float* __restrict__ Wc1, const float* __restrict__ bc1,
        const float* __restrict__ Wc2, const float* __restrict__ bc2,
        float* __restrict__ out, int tpf)
{
    __shared__ __align__(16) float sWd1[3*HIDDEN];
    __shared__ __align__(16) float sbd1[HIDDEN];
    __shared__ __align__(16) float sWd2[HIDDEN*16];
    __shared__ __align__(16) float sbd2[16];
    __shared__ __align__(16) float sWc1[HIDDEN*CINP];   // transposed [j][k], k padded
    __shared__ __align__(16) float sbc1[HIDDEN];
    __shared__ __align__(16) float sWc2[HIDDEN*4];      // [j][rgb,pad]
    __shared__ __align__(16) float sbc2[4];

    int f = blockIdx.x / tpf;
    int t = blockIdx.x - f * tpf;
    int cnt = g_counts[f];
    if (t * TILE >= cnt) return;

    int tid = threadIdx.x;

    // ---- stage weights into smem ----
    {
        const float* g = Wd1 + f*3*HIDDEN;
        for (int i = tid; i < 3*HIDDEN; i += TILE) sWd1[i] = g[i];
    }
    sbd1[tid] = bd1[f*HIDDEN + tid];
    {
        const float* g = Wd2 + f*HIDDEN*16;
        for (int i = tid; i < HIDDEN*16; i += TILE) sWd2[i] = g[i];
    }
    if (tid < 16) sbd2[tid] = bd2[f*16 + tid];
    {   // transpose Wc1 [k][j] -> sWc1 [j][k]
        const float* g = Wc1 + f*CIN*HIDDEN;
        for (int i = tid; i < CIN*HIDDEN; i += TILE) {
            int k = i / HIDDEN, j = i - k*HIDDEN;
            sWc1[j*CINP + k] = g[i];
        }
        sWc1[tid*CINP + 50] = 0.f;   // tid spans all j == 0..127
        sWc1[tid*CINP + 51] = 0.f;
    }
    sbc1[tid] = bc1[f*HIDDEN + tid];
    {
        const float* g = Wc2 + f*HIDDEN*3;
        sWc2[tid*4+0] = g[tid*3+0];
        sWc2[tid*4+1] = g[tid*3+1];
        sWc2[tid*4+2] = g[tid*3+2];
        sWc2[tid*4+3] = 0.f;
    }
    if (tid < 3) sbc2[tid] = bc2[f*3 + tid];
    if (tid == 3) sbc2[3] = 0.f;
    __syncthreads();

    int bi = t * TILE + tid;
    if (bi >= cnt) return;
    int p = g_bucket[f][bi];

    float px = pos[3*p], py = pos[3*p+1], pz = pos[3*p+2];

    // ---- fused layers 1+2: d0 = relu(pos@Wd1+bd1) @ Wd2 + bd2 ----
    // h values are computed 4 at a time and consumed immediately (no h[128]).
    float d0[16];
    #pragma unroll
    for (int q = 0; q < 16; q++) d0[q] = sbd2[q];

    #pragma unroll 4
    for (int j = 0; j < HIDDEN; j += 4) {
        float4 w0 = *(const float4*)&sWd1[0*HIDDEN + j];
        float4 w1 = *(const float4*)&sWd1[1*HIDDEN + j];
        float4 w2 = *(const float4*)&sWd1[2*HIDDEN + j];
        float4 b  = *(const float4*)&sbd1[j];
        float h0 = fmaxf(fmaf(px,w0.x,fmaf(py,w1.x,fmaf(pz,w2.x,b.x))), 0.f);
        float h1 = fmaxf(fmaf(px,w0.y,fmaf(py,w1.y,fmaf(pz,w2.y,b.y))), 0.f);
        float h2 = fmaxf(fmaf(px,w0.z,fmaf(py,w1.z,fmaf(pz,w2.z,b.z))), 0.f);
        float h3 = fmaxf(fmaf(px,w0.w,fmaf(py,w1.w,fmaf(pz,w2.w,b.w))), 0.f);

        const float4* r0p = (const float4*)&sWd2[(j+0)*16];
        const float4* r1p = (const float4*)&sWd2[(j+1)*16];
        const float4* r2p = (const float4*)&sWd2[(j+2)*16];
        const float4* r3p = (const float4*)&sWd2[(j+3)*16];
        #pragma unroll
        for (int q = 0; q < 4; q++) {
            float4 a = r0p[q];
            d0[4*q+0] = fmaf(h0, a.x, d0[4*q+0]);
            d0[4*q+1] = fmaf(h0, a.y, d0[4*q+1]);
            d0[4*q+2] = fmaf(h0, a.z, d0[4*q+2]);
            d0[4*q+3] = fmaf(h0, a.w, d0[4*q+3]);
        }
        #pragma unroll
        for (int q = 0; q < 4; q++) {
            float4 a = r1p[q];
            d0[4*q+0] = fmaf(h1, a.x, d0[4*q+0]);
            d0[4*q+1] = fmaf(h1, a.y, d0[4*q+1]);
            d0[4*q+2] = fmaf(h1, a.z, d0[4*q+2]);
            d0[4*q+3] = fmaf(h1, a.w, d0[4*q+3]);
        }
        #pragma unroll
        for (int q = 0; q < 4; q++) {
            float4 a = r2p[q];
            d0[4*q+0] = fmaf(h2, a.x, d0[4*q+0]);
            d0[4*q+1] = fmaf(h2, a.y, d0[4*q+1]);
            d0[4*q+2] = fmaf(h2, a.z, d0[4*q+2]);
            d0[4*q+3] = fmaf(h2, a.w, d0[4*q+3]);
        }
        #pragma unroll
        for (int q = 0; q < 4; q++) {
            float4 a = r3p[q];
            d0[4*q+0] = fmaf(h3, a.x, d0[4*q+0]);
            d0[4*q+1] = fmaf(h3, a.y, d0[4*q+1]);
            d0[4*q+2] = fmaf(h3, a.z, d0[4*q+2]);
            d0[4*q+3] = fmaf(h3, a.w, d0[4*q+3]);
        }
    }
    float density = expf(d0[0]);

    // ---- build cin = [dir, geo, app] (padded to 52) ----
    float cin[CINP];
    cin[0] = dir[3*p]; cin[1] = dir[3*p+1]; cin[2] = dir[3*p+2];
    #pragma unroll
    for (int g = 0; g < GEO; g++) cin[3+g] = d0[1+g];
    {
        const float4* ap = (const float4*)(app + (size_t)p*APP);
        #pragma unroll
        for (int q = 0; q < APP/4; q++) {
            float4 v = __ldg(&ap[q]);
            cin[18+4*q+0] = v.x; cin[18+4*q+1] = v.y;
            cin[18+4*q+2] = v.z; cin[18+4*q+3] = v.w;
        }
    }
    cin[50] = 0.f; cin[51] = 0.f;

    // ---- color MLP fused: rgb += relu(cin @ Wc1[:,j] + bc1[j]) * Wc2[j,:] ----
    float r0 = sbc2[0], r1 = sbc2[1], r2 = sbc2[2];
    #pragma unroll 4
    for (int j = 0; j < HIDDEN; j++) {
        float acc = sbc1[j];
        const float4* wr = (const float4*)&sWc1[j*CINP];
        #pragma unroll
        for (int q = 0; q < CINP/4; q++) {
            float4 w = wr[q];
            acc = fmaf(cin[4*q+0], w.x, acc);
            acc = fmaf(cin[4*q+1], w.y, acc);
            acc = fmaf(cin[4*q+2], w.z, acc);
            acc = fmaf(cin[4*q+3], w.w, acc);
        }
        float hc = fmaxf(acc, 0.f);
        float4 w2 = *(const float4*)&sWc2[j*4];
        r0 = fmaf(hc, w2.x, r0);
        r1 = fmaf(hc, w2.y, r1);
        r2 = fmaf(hc, w2.z, r2);
    }

    float4 o;
    o.x = density;
    o.y = 1.f / (1.f + expf(-r0));
    o.z = 1.f / (1.f + expf(-r1));
    o.w = 1.f / (1.f + expf(-r2));
    *(float4*)&out[(size_t)4*p] = o;
}

// ---------------- launch ----------------------------------------------------
extern "C" void kernel_launch(void* const* d_in, const int* in_sizes, int n_in,
                              void* d_out, int out_size) {
    const float* positions  = (const float*)d_in[0];
    const float* directions = (const float*)d_in[1];
    const float* appearance = (const float*)d_in[2];
    const float* centroids  = (const float*)d_in[3];
    const float* Wd1 = (const float*)d_in[4];
    const float* bd1 = (const float*)d_in[5];
    const float* Wd2 = (const float*)d_in[6];
    const float* bd2 = (const float*)d_in[7];
    const float* Wc1 = (const float*)d_in[8];
    const float* bc1 = (const float*)d_in[9];
    const float* Wc2 = (const float*)d_in[10];
    const float* bc2 = (const float*)d_in[11];
    float* out = (float*)d_out;

    int n = in_sizes[0] / 3;
    if (n > N_MAX) n = N_MAX;

    int tpf = (n + TILE - 1) / TILE;

    k_zero<<<1, 32>>>();
    k_assign<<<(n + 255) / 256, 256>>>(positions, centroids, n);
    k_field<<<N_FIELDS * tpf, TILE>>>(positions, directions, appearance,
                                      Wd1, bd1, Wd2, bd2, Wc1, bc1, Wc2, bc2,
                                      out, tpf);
}

// round 5
// speedup vs baseline: 1.5896x; 1.3160x over previous
#include <cuda_runtime.h>
#include <math.h>

#define N_FIELDS 8
#define HIDDEN   128
#define GEO      15
#define APP      32
#define CIN      50
#define N_MAX    524288
#define TILE     128

#define CIN_STRIDE 61     // conflict-free STS.32 writes; <=2-way A-frag LDS
#define WC1_STRIDE 132    // conflict-free B-frag LDS

// ---- dynamic smem layout (float offsets) ----
#define OFF_WD1   0        // 3*128 = 384
#define OFF_BD1   384      // 128
#define OFF_WD2   512      // 128*16 = 2048
#define OFF_BD2   2560     // 16
#define OFF_BC1   2576     // 128
#define OFF_BC2   2704     // 4
#define OFF_WC2   2708     // 128*4 (float4[128]) ; byte 10832 is 16B aligned
#define OFF_WC1   3220     // 56*132 = 7392 (tf32 bits)
#define OFF_CIN   10612    // 128*61 = 7808 (tf32 bits)
#define OFF_PIDX  18420    // 128 ints
#define SMEM_FLOATS 18548
#define SMEM_BYTES  (SMEM_FLOATS * 4)

// ---------------- device scratch ----------------
__device__ int g_counts[N_FIELDS];
__device__ int g_bucket[N_FIELDS][N_MAX];

__global__ void k_zero() {
    if (threadIdx.x < N_FIELDS) g_counts[threadIdx.x] = 0;
}

__global__ void k_assign(const float* __restrict__ pos,
                         const float* __restrict__ cent, int n) {
    int i = blockIdx.x * blockDim.x + threadIdx.x;
    unsigned act = __ballot_sync(0xffffffffu, i < n);
    if (i >= n) return;
    float px = pos[3*i], py = pos[3*i+1], pz = pos[3*i+2];
    int best = 0; float bd = 3.402823e38f;
    #pragma unroll
    for (int c = 0; c < N_FIELDS; c++) {
        float dx = px - __ldg(&cent[3*c+0]);
        float dy = py - __ldg(&cent[3*c+1]);
        float dz = pz - __ldg(&cent[3*c+2]);
        float d = dx*dx + dy*dy + dz*dz;
        if (d < bd) { bd = d; best = c; }
    }
    unsigned peers  = __match_any_sync(act, best);
    int leader = __ffs(peers) - 1;
    int lane   = threadIdx.x & 31;
    int base = 0;
    if (lane == leader) base = atomicAdd(&g_counts[best], __popc(peers));
    base = __shfl_sync(peers, base, leader);
    g_bucket[best][base + __popc(peers & ((1u << lane) - 1u))] = i;
}

// ---- helpers ----
__device__ __forceinline__ unsigned f2tf32(float x) {
    unsigned r;
    asm("cvt.rna.tf32.f32 %0, %1;" : "=r"(r) : "f"(x));
    return r;
}
__device__ __forceinline__ void mma_tf32(float& c0, float& c1, float& c2, float& c3,
                                         unsigned a0, unsigned a1, unsigned a2, unsigned a3,
                                         unsigned b0, unsigned b1) {
    asm("mma.sync.aligned.m16n8k8.row.col.f32.tf32.tf32.f32 "
        "{%0,%1,%2,%3},{%4,%5,%6,%7},{%8,%9},{%0,%1,%2,%3};"
        : "+f"(c0), "+f"(c1), "+f"(c2), "+f"(c3)
        : "r"(a0), "r"(a1), "r"(a2), "r"(a3), "r"(b0), "r"(b1));
}

// ---------------- kernel 2 ----------------
__global__ void __launch_bounds__(TILE)
k_field(const float* __restrict__ pos, const float* __restrict__ dir,
        const float* __restrict__ app,
        const float* __restrict__ Wd1, const float* __restrict__ bd1,
        const float* __restrict__ Wd2, const float* __restrict__ bd2,
        const float* __restrict__ Wc1, const float* __restrict__ bc1,
        const float* __restrict__ Wc2, const float* __restrict__ bc2,
        float* __restrict__ out, int tpf)
{
    extern __shared__ float sm[];
    int* sPidx = (int*)(sm + OFF_PIDX);

    int f = blockIdx.x / tpf;
    int t = blockIdx.x - f * tpf;
    int cnt = g_counts[f];
    if (t * TILE >= cnt) return;

    int tid = threadIdx.x;

    // ---- stage weights ----
    {
        const float* g = Wd1 + f*3*HIDDEN;
        for (int i = tid; i < 3*HIDDEN; i += TILE) sm[OFF_WD1 + i] = g[i];
    }
    sm[OFF_BD1 + tid] = bd1[f*HIDDEN + tid];
    {
        const float* g = Wd2 + f*HIDDEN*16;
        for (int i = tid; i < HIDDEN*16; i += TILE) sm[OFF_WD2 + i] = g[i];
    }
    if (tid < 16) sm[OFF_BD2 + tid] = bd2[f*16 + tid];
    sm[OFF_BC1 + tid] = bc1[f*HIDDEN + tid];
    if (tid < 3) sm[OFF_BC2 + tid] = bc2[f*3 + tid];
    if (tid == 3) sm[OFF_BC2 + 3] = 0.f;
    {   // Wc1 [k][n] -> tf32 bits, stride 132 (no transpose needed)
        const float* g = Wc1 + f*CIN*HIDDEN;
        for (int i = tid; i < CIN*HIDDEN; i += TILE) {
            int k = i >> 7, nn = i & 127;
            sm[OFF_WC1 + k*WC1_STRIDE + nn] = __uint_as_float(f2tf32(g[i]));
        }
        for (int i = tid; i < 6*WC1_STRIDE; i += TILE)  // zero K rows 50..55
            sm[OFF_WC1 + 50*WC1_STRIDE + i] = 0.f;
    }
    {
        const float* g = Wc2 + f*HIDDEN*3;
        sm[OFF_WC2 + tid*4+0] = g[tid*3+0];
        sm[OFF_WC2 + tid*4+1] = g[tid*3+1];
        sm[OFF_WC2 + tid*4+2] = g[tid*3+2];
        sm[OFF_WC2 + tid*4+3] = 0.f;
    }
    __syncthreads();

    // ---- scalar phase: density (fused L1+L2) + CIN row ----
    int bi = t * TILE + tid;
    bool valid = (bi < cnt);
    int p = g_bucket[f][valid ? bi : (cnt - 1)];
    sPidx[tid] = valid ? p : -1;

    float px = pos[3*p], py = pos[3*p+1], pz = pos[3*p+2];

    float d0[16];
    #pragma unroll
    for (int q = 0; q < 16; q++) d0[q] = sm[OFF_BD2 + q];

    #pragma unroll 4
    for (int j = 0; j < HIDDEN; j += 4) {
        float4 w0 = *(const float4*)&sm[OFF_WD1 + 0*HIDDEN + j];
        float4 w1 = *(const float4*)&sm[OFF_WD1 + 1*HIDDEN + j];
        float4 w2 = *(const float4*)&sm[OFF_WD1 + 2*HIDDEN + j];
        float4 b  = *(const float4*)&sm[OFF_BD1 + j];
        float h0 = fmaxf(fmaf(px,w0.x,fmaf(py,w1.x,fmaf(pz,w2.x,b.x))), 0.f);
        float h1 = fmaxf(fmaf(px,w0.y,fmaf(py,w1.y,fmaf(pz,w2.y,b.y))), 0.f);
        float h2 = fmaxf(fmaf(px,w0.z,fmaf(py,w1.z,fmaf(pz,w2.z,b.z))), 0.f);
        float h3 = fmaxf(fmaf(px,w0.w,fmaf(py,w1.w,fmaf(pz,w2.w,b.w))), 0.f);
        const float4* r0p = (const float4*)&sm[OFF_WD2 + (j+0)*16];
        const float4* r1p = (const float4*)&sm[OFF_WD2 + (j+1)*16];
        const float4* r2p = (const float4*)&sm[OFF_WD2 + (j+2)*16];
        const float4* r3p = (const float4*)&sm[OFF_WD2 + (j+3)*16];
        #pragma unroll
        for (int q = 0; q < 4; q++) {
            float4 a = r0p[q];
            d0[4*q+0] = fmaf(h0,a.x,d0[4*q+0]); d0[4*q+1] = fmaf(h0,a.y,d0[4*q+1]);
            d0[4*q+2] = fmaf(h0,a.z,d0[4*q+2]); d0[4*q+3] = fmaf(h0,a.w,d0[4*q+3]);
        }
        #pragma unroll
        for (int q = 0; q < 4; q++) {
            float4 a = r1p[q];
            d0[4*q+0] = fmaf(h1,a.x,d0[4*q+0]); d0[4*q+1] = fmaf(h1,a.y,d0[4*q+1]);
            d0[4*q+2] = fmaf(h1,a.z,d0[4*q+2]); d0[4*q+3] = fmaf(h1,a.w,d0[4*q+3]);
        }
        #pragma unroll
        for (int q = 0; q < 4; q++) {
            float4 a = r2p[q];
            d0[4*q+0] = fmaf(h2,a.x,d0[4*q+0]); d0[4*q+1] = fmaf(h2,a.y,d0[4*q+1]);
            d0[4*q+2] = fmaf(h2,a.z,d0[4*q+2]); d0[4*q+3] = fmaf(h2,a.w,d0[4*q+3]);
        }
        #pragma unroll
        for (int q = 0; q < 4; q++) {
            float4 a = r3p[q];
            d0[4*q+0] = fmaf(h3,a.x,d0[4*q+0]); d0[4*q+1] = fmaf(h3,a.y,d0[4*q+1]);
            d0[4*q+2] = fmaf(h3,a.z,d0[4*q+2]); d0[4*q+3] = fmaf(h3,a.w,d0[4*q+3]);
        }
    }
    if (valid) out[(size_t)4*p] = expf(d0[0]);   // density

    // ---- write CIN row as tf32 bits (stride 61, conflict-free) ----
    {
        float cv[56];
        cv[0] = dir[3*p]; cv[1] = dir[3*p+1]; cv[2] = dir[3*p+2];
        #pragma unroll
        for (int g2 = 0; g2 < GEO; g2++) cv[3+g2] = d0[1+g2];
        const float4* ap = (const float4*)(app + (size_t)p*APP);
        #pragma unroll
        for (int q = 0; q < APP/4; q++) {
            float4 v = __ldg(&ap[q]);
            cv[18+4*q+0] = v.x; cv[18+4*q+1] = v.y;
            cv[18+4*q+2] = v.z; cv[18+4*q+3] = v.w;
        }
        #pragma unroll
        for (int c = CIN; c < 56; c++) cv[c] = 0.f;
        float* row = sm + OFF_CIN + tid*CIN_STRIDE;
        #pragma unroll
        for (int k = 0; k < 56; k++) row[k] = __uint_as_float(f2tf32(cv[k]));
    }
    __syncthreads();

    // ---- tensor phase: HC = relu(CIN @ Wc1 + bc1); RGB = HC @ Wc2 fused ----
    int lane = tid & 31;
    int wid  = tid >> 5;
    int g    = lane >> 2;    // groupID
    int tg   = lane & 3;     // threadID in group
    int wbase = wid * 32;

    const unsigned* C32 = (const unsigned*)(sm + OFF_CIN);
    const unsigned* W32 = (const unsigned*)(sm + OFF_WC1);
    const float4*  WC2v = (const float4*)(sm + OFF_WC2);

    // A fragments: loaded once, reused for all 16 n-blocks
    unsigned a[2][7][4];
    #pragma unroll
    for (int mt = 0; mt < 2; mt++) {
        int r0 = wbase + 16*mt + g;
        #pragma unroll
        for (int ks = 0; ks < 7; ks++) {
            int c = 8*ks + tg;
            a[mt][ks][0] = C32[(r0    )*CIN_STRIDE + c    ];
            a[mt][ks][1] = C32[(r0 + 8)*CIN_STRIDE + c    ];
            a[mt][ks][2] = C32[(r0    )*CIN_STRIDE + c + 4];
            a[mt][ks][3] = C32[(r0 + 8)*CIN_STRIDE + c + 4];
        }
    }

    float acc[4][3];   // rows wbase+g+{0,8,16,24} x rgb
    #pragma unroll
    for (int q = 0; q < 4; q++) { acc[q][0] = 0.f; acc[q][1] = 0.f; acc[q][2] = 0.f; }

    #pragma unroll 2
    for (int nb = 0; nb < 16; nb++) {
        int coln = 8*nb + g;
        unsigned b[7][2];
        #pragma unroll
        for (int ks = 0; ks < 7; ks++) {
            b[ks][0] = W32[(8*ks + tg    )*WC1_STRIDE + coln];
            b[ks][1] = W32[(8*ks + tg + 4)*WC1_STRIDE + coln];
        }
        int j0 = 8*nb + 2*tg;
        float bj0 = sm[OFF_BC1 + j0], bj1 = sm[OFF_BC1 + j0 + 1];
        float4 w0 = WC2v[j0];
        float4 w1 = WC2v[j0 + 1];

        #pragma unroll
        for (int mt = 0; mt < 2; mt++) {
            float c0 = 0.f, c1 = 0.f, c2 = 0.f, c3 = 0.f;
            #pragma unroll
            for (int ks = 0; ks < 7; ks++)
                mma_tf32(c0, c1, c2, c3,
                         a[mt][ks][0], a[mt][ks][1], a[mt][ks][2], a[mt][ks][3],
                         b[ks][0], b[ks][1]);
            float h00 = fmaxf(c0 + bj0, 0.f);   // row g,   col j0
            float h01 = fmaxf(c1 + bj1, 0.f);   // row g,   col j0+1
            float h10 = fmaxf(c2 + bj0, 0.f);   // row g+8, col j0
            float h11 = fmaxf(c3 + bj1, 0.f);   // row g+8, col j0+1
            int q0 = 2*mt, q1 = 2*mt + 1;
            acc[q0][0] = fmaf(h00, w0.x, fmaf(h01, w1.x, acc[q0][0]));
            acc[q0][1] = fmaf(h00, w0.y, fmaf(h01, w1.y, acc[q0][1]));
            acc[q0][2] = fmaf(h00, w0.z, fmaf(h01, w1.z, acc[q0][2]));
            acc[q1][0] = fmaf(h10, w0.x, fmaf(h11, w1.x, acc[q1][0]));
            acc[q1][1] = fmaf(h10, w0.y, fmaf(h11, w1.y, acc[q1][1]));
            acc[q1][2] = fmaf(h10, w0.z, fmaf(h11, w1.z, acc[q1][2]));
        }
    }

    // reduce over the 4 lanes of each quad (j-space partials)
    #pragma unroll
    for (int q = 0; q < 4; q++)
        #pragma unroll
        for (int c = 0; c < 3; c++) {
            float v = acc[q][c];
            v += __shfl_xor_sync(0xffffffffu, v, 1);
            v += __shfl_xor_sync(0xffffffffu, v, 2);
            acc[q][c] = v;
        }

    // lane tg writes row wbase + g + 8*tg
    {
        int row = wbase + g + 8*tg;
        float r0 = acc[tg][0], r1 = acc[tg][1], r2 = acc[tg][2];
        int pp = sPidx[row];
        if (pp >= 0) {
            r0 += sm[OFF_BC2 + 0];
            r1 += sm[OFF_BC2 + 1];
            r2 += sm[OFF_BC2 + 2];
            out[(size_t)4*pp + 1] = 1.f / (1.f + expf(-r0));
            out[(size_t)4*pp + 2] = 1.f / (1.f + expf(-r1));
            out[(size_t)4*pp + 3] = 1.f / (1.f + expf(-r2));
        }
    }
}

// ---------------- launch ----------------
extern "C" void kernel_launch(void* const* d_in, const int* in_sizes, int n_in,
                              void* d_out, int out_size) {
    const float* positions  = (const float*)d_in[0];
    const float* directions = (const float*)d_in[1];
    const float* appearance = (const float*)d_in[2];
    const float* centroids  = (const float*)d_in[3];
    const float* Wd1 = (const float*)d_in[4];
    const float* bd1 = (const float*)d_in[5];
    const float* Wd2 = (const float*)d_in[6];
    const float* bd2 = (const float*)d_in[7];
    const float* Wc1 = (const float*)d_in[8];
    const float* bc1 = (const float*)d_in[9];
    const float* Wc2 = (const float*)d_in[10];
    const float* bc2 = (const float*)d_in[11];
    float* out = (float*)d_out;

    int n = in_sizes[0] / 3;
    if (n > N_MAX) n = N_MAX;
    int tpf = (n + TILE - 1) / TILE;

    cudaFuncSetAttribute(k_field, cudaFuncAttributeMaxDynamicSharedMemorySize,
                         SMEM_BYTES);

    k_zero<<<1, 32>>>();
    k_assign<<<(n + 255) / 256, 256>>>(positions, centroids, n);
    k_field<<<N_FIELDS * tpf, TILE, SMEM_BYTES>>>(positions, directions, appearance,
                                                  Wd1, bd1, Wd2, bd2, Wc1, bc1,
                                                  Wc2, bc2, out, tpf);
}

// round 6
// speedup vs baseline: 2.0430x; 1.2852x over previous
#include <cuda_runtime.h>
#include <cuda_fp16.h>
#include <math.h>

#define N_FIELDS 8
#define HIDDEN   128
#define GEO      15
#define APP      32
#define CIN      50
#define N_MAX    524288
#define TILE     128

#define CINW_STRIDE 44    // u32 words/row; 44 mod 32 = 12 -> conflict-free A-frags
#define WC1W_STRIDE 136   // u32 words/row; 136 mod 32 = 8 -> conflict-free B-frags

// ---- dynamic smem layout (32-bit word offsets) ----
#define OFF_WD1   0        // 384 floats
#define OFF_BD1   384      // 128
#define OFF_WD2   512      // 2048
#define OFF_BD2   2560     // 16
#define OFF_BC1   2576     // 128
#define OFF_BC2   2704     // 4
#define OFF_WC2   2708     // 512 (float4[128]); byte 10832, 16B aligned
#define OFF_WC1   3220     // 32*136 = 4352 words of half2
#define OFF_CINW  7572     // 128*44 = 5632 words of half2; byte 30288, 16B aligned
#define OFF_PIDX  13204    // 128 ints
#define SMEM_WORDS 13332
#define SMEM_BYTES (SMEM_WORDS * 4)

// ---------------- device scratch ----------------
__device__ int g_counts[N_FIELDS];
__device__ int g_bucket[N_FIELDS][N_MAX];

__global__ void k_zero() {
    if (threadIdx.x < N_FIELDS) g_counts[threadIdx.x] = 0;
}

__global__ void k_assign(const float* __restrict__ pos,
                         const float* __restrict__ cent, int n) {
    int i = blockIdx.x * blockDim.x + threadIdx.x;
    unsigned act = __ballot_sync(0xffffffffu, i < n);
    if (i >= n) return;
    float px = pos[3*i], py = pos[3*i+1], pz = pos[3*i+2];
    int best = 0; float bd = 3.402823e38f;
    #pragma unroll
    for (int c = 0; c < N_FIELDS; c++) {
        float dx = px - __ldg(&cent[3*c+0]);
        float dy = py - __ldg(&cent[3*c+1]);
        float dz = pz - __ldg(&cent[3*c+2]);
        float d = dx*dx + dy*dy + dz*dz;
        if (d < bd) { bd = d; best = c; }
    }
    unsigned peers  = __match_any_sync(act, best);
    int leader = __ffs(peers) - 1;
    int lane   = threadIdx.x & 31;
    int base = 0;
    if (lane == leader) base = atomicAdd(&g_counts[best], __popc(peers));
    base = __shfl_sync(peers, base, leader);
    g_bucket[best][base + __popc(peers & ((1u << lane) - 1u))] = i;
}

// ---- helpers ----
__device__ __forceinline__ unsigned packh2(float lo, float hi) {
    __half2 h = __floats2half2_rn(lo, hi);   // .x = lo (low 16 bits)
    return *(unsigned*)&h;
}
__device__ __forceinline__ void mma_f16(float& c0, float& c1, float& c2, float& c3,
                                        unsigned a0, unsigned a1, unsigned a2, unsigned a3,
                                        unsigned b0, unsigned b1) {
    asm("mma.sync.aligned.m16n8k16.row.col.f32.f16.f16.f32 "
        "{%0,%1,%2,%3},{%4,%5,%6,%7},{%8,%9},{%0,%1,%2,%3};"
        : "+f"(c0), "+f"(c1), "+f"(c2), "+f"(c3)
        : "r"(a0), "r"(a1), "r"(a2), "r"(a3), "r"(b0), "r"(b1));
}

// ---------------- kernel 2 ----------------
__global__ void __launch_bounds__(TILE)
k_field(const float* __restrict__ pos, const float* __restrict__ dir,
        const float* __restrict__ app,
        const float* __restrict__ Wd1, const float* __restrict__ bd1,
        const float* __restrict__ Wd2, const float* __restrict__ bd2,
        const float* __restrict__ Wc1, const float* __restrict__ bc1,
        const float* __restrict__ Wc2, const float* __restrict__ bc2,
        float* __restrict__ out, int tpf)
{
    extern __shared__ float sm[];
    unsigned* smw = (unsigned*)sm;
    int* sPidx = (int*)(sm + OFF_PIDX);

    int f = blockIdx.x / tpf;
    int t = blockIdx.x - f * tpf;
    int cnt = g_counts[f];
    if (t * TILE >= cnt) return;

    int tid = threadIdx.x;

    // ---- stage weights ----
    {
        const float* g = Wd1 + f*3*HIDDEN;
        for (int i = tid; i < 3*HIDDEN; i += TILE) sm[OFF_WD1 + i] = g[i];
    }
    sm[OFF_BD1 + tid] = bd1[f*HIDDEN + tid];
    {
        const float* g = Wd2 + f*HIDDEN*16;
        for (int i = tid; i < HIDDEN*16; i += TILE) sm[OFF_WD2 + i] = g[i];
    }
    if (tid < 16) sm[OFF_BD2 + tid] = bd2[f*16 + tid];
    sm[OFF_BC1 + tid] = bc1[f*HIDDEN + tid];
    if (tid < 3) sm[OFF_BC2 + tid] = bc2[f*3 + tid];
    if (tid == 3) sm[OFF_BC2 + 3] = 0.f;
    {   // Wc1 [k=50][n=128] -> half2 words [kp=32][n=128], kp pairs (2kp, 2kp+1)
        const float* g = Wc1 + f*CIN*HIDDEN;
        for (int i = tid; i < 32*HIDDEN; i += TILE) {
            int kp = i >> 7, nn = i & 127;
            unsigned w = 0u;
            if (kp < 25) {  // k=2kp,2kp+1 both < 50
                float lo = g[(2*kp)*HIDDEN + nn];
                float hi = g[(2*kp+1)*HIDDEN + nn];
                w = packh2(lo, hi);
            }
            smw[OFF_WC1 + kp*WC1W_STRIDE + nn] = w;
        }
    }
    {
        const float* g = Wc2 + f*HIDDEN*3;
        sm[OFF_WC2 + tid*4+0] = g[tid*3+0];
        sm[OFF_WC2 + tid*4+1] = g[tid*3+1];
        sm[OFF_WC2 + tid*4+2] = g[tid*3+2];
        sm[OFF_WC2 + tid*4+3] = 0.f;
    }
    __syncthreads();

    // ---- scalar phase: density (fused L1+L2) ----
    int bi = t * TILE + tid;
    bool valid = (bi < cnt);
    int p = g_bucket[f][valid ? bi : (cnt - 1)];
    sPidx[tid] = valid ? p : -1;

    float px = pos[3*p], py = pos[3*p+1], pz = pos[3*p+2];

    float d0[16];
    #pragma unroll
    for (int q = 0; q < 16; q++) d0[q] = sm[OFF_BD2 + q];

    #pragma unroll 4
    for (int j = 0; j < HIDDEN; j += 4) {
        float4 w0 = *(const float4*)&sm[OFF_WD1 + 0*HIDDEN + j];
        float4 w1 = *(const float4*)&sm[OFF_WD1 + 1*HIDDEN + j];
        float4 w2 = *(const float4*)&sm[OFF_WD1 + 2*HIDDEN + j];
        float4 b  = *(const float4*)&sm[OFF_BD1 + j];
        float h0 = fmaxf(fmaf(px,w0.x,fmaf(py,w1.x,fmaf(pz,w2.x,b.x))), 0.f);
        float h1 = fmaxf(fmaf(px,w0.y,fmaf(py,w1.y,fmaf(pz,w2.y,b.y))), 0.f);
        float h2 = fmaxf(fmaf(px,w0.z,fmaf(py,w1.z,fmaf(pz,w2.z,b.z))), 0.f);
        float h3 = fmaxf(fmaf(px,w0.w,fmaf(py,w1.w,fmaf(pz,w2.w,b.w))), 0.f);
        const float4* r0p = (const float4*)&sm[OFF_WD2 + (j+0)*16];
        const float4* r1p = (const float4*)&sm[OFF_WD2 + (j+1)*16];
        const float4* r2p = (const float4*)&sm[OFF_WD2 + (j+2)*16];
        const float4* r3p = (const float4*)&sm[OFF_WD2 + (j+3)*16];
        #pragma unroll
        for (int q = 0; q < 4; q++) {
            float4 a = r0p[q];
            d0[4*q+0] = fmaf(h0,a.x,d0[4*q+0]); d0[4*q+1] = fmaf(h0,a.y,d0[4*q+1]);
            d0[4*q+2] = fmaf(h0,a.z,d0[4*q+2]); d0[4*q+3] = fmaf(h0,a.w,d0[4*q+3]);
        }
        #pragma unroll
        for (int q = 0; q < 4; q++) {
            float4 a = r1p[q];
            d0[4*q+0] = fmaf(h1,a.x,d0[4*q+0]); d0[4*q+1] = fmaf(h1,a.y,d0[4*q+1]);
            d0[4*q+2] = fmaf(h1,a.z,d0[4*q+2]); d0[4*q+3] = fmaf(h1,a.w,d0[4*q+3]);
        }
        #pragma unroll
        for (int q = 0; q < 4; q++) {
            float4 a = r2p[q];
            d0[4*q+0] = fmaf(h2,a.x,d0[4*q+0]); d0[4*q+1] = fmaf(h2,a.y,d0[4*q+1]);
            d0[4*q+2] = fmaf(h2,a.z,d0[4*q+2]); d0[4*q+3] = fmaf(h2,a.w,d0[4*q+3]);
        }
        #pragma unroll
        for (int q = 0; q < 4; q++) {
            float4 a = r3p[q];
            d0[4*q+0] = fmaf(h3,a.x,d0[4*q+0]); d0[4*q+1] = fmaf(h3,a.y,d0[4*q+1]);
            d0[4*q+2] = fmaf(h3,a.z,d0[4*q+2]); d0[4*q+3] = fmaf(h3,a.w,d0[4*q+3]);
        }
    }
    if (valid) out[(size_t)4*p] = expf(d0[0]);   // density

    // ---- build CIN row as packed half2 (32 words, K padded to 64) ----
    {
        float cv[56];
        cv[0] = dir[3*p]; cv[1] = dir[3*p+1]; cv[2] = dir[3*p+2];
        #pragma unroll
        for (int g2 = 0; g2 < GEO; g2++) cv[3+g2] = d0[1+g2];
        const float4* ap = (const float4*)(app + (size_t)p*APP);
        #pragma unroll
        for (int q = 0; q < APP/4; q++) {
            float4 v = __ldg(&ap[q]);
            cv[18+4*q+0] = v.x; cv[18+4*q+1] = v.y;
            cv[18+4*q+2] = v.z; cv[18+4*q+3] = v.w;
        }
        #pragma unroll
        for (int c = CIN; c < 56; c++) cv[c] = 0.f;
        unsigned w[32];
        #pragma unroll
        for (int q = 0; q < 28; q++) w[q] = packh2(cv[2*q], cv[2*q+1]);
        #pragma unroll
        for (int q = 28; q < 32; q++) w[q] = 0u;
        uint4* row = (uint4*)(smw + OFF_CINW + tid*CINW_STRIDE);
        #pragma unroll
        for (int q = 0; q < 8; q++)
            row[q] = make_uint4(w[4*q], w[4*q+1], w[4*q+2], w[4*q+3]);
    }
    __syncwarp();   // tensor phase only reads this warp's own 32 rows

    // ---- tensor phase: HC = relu(CIN @ Wc1 + bc1); RGB = HC @ Wc2 fused ----
    int lane = tid & 31;
    int wid  = tid >> 5;
    int g    = lane >> 2;    // groupID
    int tg   = lane & 3;     // threadID in group
    int wbase = wid * 32;

    const unsigned* C32 = smw + OFF_CINW;
    const unsigned* W32 = smw + OFF_WC1;
    const float4*  WC2v = (const float4*)(sm + OFF_WC2);

    // A fragments: loaded once, reused for all 16 n-blocks. 2 mt x 4 ks x 4 regs.
    unsigned a[2][4][4];
    #pragma unroll
    for (int mt = 0; mt < 2; mt++) {
        int r0 = wbase + 16*mt + g;
        #pragma unroll
        for (int ks = 0; ks < 4; ks++) {
            int c = 8*ks + tg;
            a[mt][ks][0] = C32[(r0    )*CINW_STRIDE + c    ];
            a[mt][ks][1] = C32[(r0 + 8)*CINW_STRIDE + c    ];
            a[mt][ks][2] = C32[(r0    )*CINW_STRIDE + c + 4];
            a[mt][ks][3] = C32[(r0 + 8)*CINW_STRIDE + c + 4];
        }
    }

    float acc[4][3];   // rows wbase+g+{0,8,16,24} x rgb
    #pragma unroll
    for (int q = 0; q < 4; q++) { acc[q][0] = 0.f; acc[q][1] = 0.f; acc[q][2] = 0.f; }

    #pragma unroll 2
    for (int nb = 0; nb < 16; nb++) {
        int coln = 8*nb + g;
        unsigned b[4][2];
        #pragma unroll
        for (int ks = 0; ks < 4; ks++) {
            b[ks][0] = W32[(8*ks + tg    )*WC1W_STRIDE + coln];
            b[ks][1] = W32[(8*ks + tg + 4)*WC1W_STRIDE + coln];
        }
        int j0 = 8*nb + 2*tg;
        float bj0 = sm[OFF_BC1 + j0], bj1 = sm[OFF_BC1 + j0 + 1];
        float4 w0 = WC2v[j0];
        float4 w1 = WC2v[j0 + 1];

        #pragma unroll
        for (int mt = 0; mt < 2; mt++) {
            // k-split accumulators: two independent 2-deep chains
            float cA0 = 0.f, cA1 = 0.f, cA2 = 0.f, cA3 = 0.f;
            float cB0 = 0.f, cB1 = 0.f, cB2 = 0.f, cB3 = 0.f;
            mma_f16(cA0, cA1, cA2, cA3,
                    a[mt][0][0], a[mt][0][1], a[mt][0][2], a[mt][0][3],
                    b[0][0], b[0][1]);
            mma_f16(cB0, cB1, cB2, cB3,
                    a[mt][1][0], a[mt][1][1], a[mt][1][2], a[mt][1][3],
                    b[1][0], b[1][1]);
            mma_f16(cA0, cA1, cA2, cA3,
                    a[mt][2][0], a[mt][2][1], a[mt][2][2], a[mt][2][3],
                    b[2][0], b[2][1]);
            mma_f16(cB0, cB1, cB2, cB3,
                    a[mt][3][0], a[mt][3][1], a[mt][3][2], a[mt][3][3],
                    b[3][0], b[3][1]);
            float h00 = fmaxf(cA0 + cB0 + bj0, 0.f);   // row g,   col j0
            float h01 = fmaxf(cA1 + cB1 + bj1, 0.f);   // row g,   col j0+1
            float h10 = fmaxf(cA2 + cB2 + bj0, 0.f);   // row g+8, col j0
            float h11 = fmaxf(cA3 + cB3 + bj1, 0.f);   // row g+8, col j0+1
            int q0 = 2*mt, q1 = 2*mt + 1;
            acc[q0][0] = fmaf(h00, w0.x, fmaf(h01, w1.x, acc[q0][0]));
            acc[q0][1] = fmaf(h00, w0.y, fmaf(h01, w1.y, acc[q0][1]));
            acc[q0][2] = fmaf(h00, w0.z, fmaf(h01, w1.z, acc[q0][2]));
            acc[q1][0] = fmaf(h10, w0.x, fmaf(h11, w1.x, acc[q1][0]));
            acc[q1][1] = fmaf(h10, w0.y, fmaf(h11, w1.y, acc[q1][1]));
            acc[q1][2] = fmaf(h10, w0.z, fmaf(h11, w1.z, acc[q1][2]));
        }
    }

    // reduce over the 4 lanes of each quad (j-space partials)
    #pragma unroll
    for (int q = 0; q < 4; q++)
        #pragma unroll
        for (int c = 0; c < 3; c++) {
            float v = acc[q][c];
            v += __shfl_xor_sync(0xffffffffu, v, 1);
            v += __shfl_xor_sync(0xffffffffu, v, 2);
            acc[q][c] = v;
        }

    // lane tg writes row wbase + g + 8*tg
    {
        int row = wbase + g + 8*tg;
        float r0 = acc[tg][0], r1 = acc[tg][1], r2 = acc[tg][2];
        int pp = sPidx[row];
        if (pp >= 0) {
            r0 += sm[OFF_BC2 + 0];
            r1 += sm[OFF_BC2 + 1];
            r2 += sm[OFF_BC2 + 2];
            out[(size_t)4*pp + 1] = 1.f / (1.f + expf(-r0));
            out[(size_t)4*pp + 2] = 1.f / (1.f + expf(-r1));
            out[(size_t)4*pp + 3] = 1.f / (1.f + expf(-r2));
        }
    }
}

// ---------------- launch ----------------
extern "C" void kernel_launch(void* const* d_in, const int* in_sizes, int n_in,
                              void* d_out, int out_size) {
    const float* positions  = (const float*)d_in[0];
    const float* directions = (const float*)d_in[1];
    const float* appearance = (const float*)d_in[2];
    const float* centroids  = (const float*)d_in[3];
    const float* Wd1 = (const float*)d_in[4];
    const float* bd1 = (const float*)d_in[5];
    const float* Wd2 = (const float*)d_in[6];
    const float* bd2 = (const float*)d_in[7];
    const float* Wc1 = (const float*)d_in[8];
    const float* bc1 = (const float*)d_in[9];
    const float* Wc2 = (const float*)d_in[10];
    const float* bc2 = (const float*)d_in[11];
    float* out = (float*)d_out;

    int n = in_sizes[0] / 3;
    if (n > N_MAX) n = N_MAX;
    int tpf = (n + TILE - 1) / TILE;

    cudaFuncSetAttribute(k_field, cudaFuncAttributeMaxDynamicSharedMemorySize,
                         SMEM_BYTES);

    k_zero<<<1, 32>>>();
    k_assign<<<(n + 255) / 256, 256>>>(positions, centroids, n);
    k_field<<<N_FIELDS * tpf, TILE, SMEM_BYTES>>>(positions, directions, appearance,
                                                  Wd1, bd1, Wd2, bd2, Wc1, bc1,
                                                  Wc2, bc2, out, tpf);
}

// round 7
// speedup vs baseline: 2.4190x; 1.1841x over previous
#include <cuda_runtime.h>
#include <cuda_fp16.h>
#include <math.h>

#define N_FIELDS 8
#define HIDDEN   128
#define GEO      15
#define APP      32
#define CIN      50
#define N_MAX    524288
#define TILE     128

#define H_STRIDE   68    // u32 words/row (h fp16, 64 used); 4g+tg bank pattern
#define WD2_STRIDE 24    // 24*tg+g covers all banks
#define WC1_STRIDE 136   // 136 mod 32 = 8 -> conflict-free B-frags
#define D0_STRIDE  20    // fp32 scratch; float4 readback conflict-free

// ---- dynamic smem layout (32-bit word offsets) ----
#define OFF_WD1    0       // 384
#define OFF_BD1    384     // 128
#define OFF_BD2    512     // 16
#define OFF_BC1    528     // 128
#define OFF_BC2    656     // 4
#define OFF_WC2    660     // 512 (float4[128]); byte 2640, 16B aligned
#define OFF_WD2H   1172    // 64*24 = 1536 (half2 of Wd2)
#define OFF_WC1    2708    // 32*136 = 4352 (half2 of Wc1)
#define OFF_H      7060    // 128*68 = 8704 (h fp16; later reused for CIN) byte 28240
#define OFF_D0S    15764   // 128*20 = 2560 (fp32 d0 scratch) byte 63056
#define OFF_PIDX   18324   // 128 ints
#define SMEM_WORDS 18452
#define SMEM_BYTES (SMEM_WORDS * 4)

// ---------------- device scratch ----------------
__device__ int g_counts[N_FIELDS];
__device__ int g_bucket[N_FIELDS][N_MAX];

__global__ void k_zero() {
    if (threadIdx.x < N_FIELDS) g_counts[threadIdx.x] = 0;
}

__global__ void k_assign(const float* __restrict__ pos,
                         const float* __restrict__ cent, int n) {
    int i = blockIdx.x * blockDim.x + threadIdx.x;
    unsigned act = __ballot_sync(0xffffffffu, i < n);
    if (i >= n) return;
    float px = pos[3*i], py = pos[3*i+1], pz = pos[3*i+2];
    int best = 0; float bd = 3.402823e38f;
    #pragma unroll
    for (int c = 0; c < N_FIELDS; c++) {
        float dx = px - __ldg(&cent[3*c+0]);
        float dy = py - __ldg(&cent[3*c+1]);
        float dz = pz - __ldg(&cent[3*c+2]);
        float d = dx*dx + dy*dy + dz*dz;
        if (d < bd) { bd = d; best = c; }
    }
    unsigned peers  = __match_any_sync(act, best);
    int leader = __ffs(peers) - 1;
    int lane   = threadIdx.x & 31;
    int base = 0;
    if (lane == leader) base = atomicAdd(&g_counts[best], __popc(peers));
    base = __shfl_sync(peers, base, leader);
    g_bucket[best][base + __popc(peers & ((1u << lane) - 1u))] = i;
}

// ---- helpers ----
__device__ __forceinline__ unsigned packh2(float lo, float hi) {
    __half2 h = __floats2half2_rn(lo, hi);
    return *(unsigned*)&h;
}
__device__ __forceinline__ void mma_f16(float& c0, float& c1, float& c2, float& c3,
                                        unsigned a0, unsigned a1, unsigned a2, unsigned a3,
                                        unsigned b0, unsigned b1) {
    asm("mma.sync.aligned.m16n8k16.row.col.f32.f16.f16.f32 "
        "{%0,%1,%2,%3},{%4,%5,%6,%7},{%8,%9},{%0,%1,%2,%3};"
        : "+f"(c0), "+f"(c1), "+f"(c2), "+f"(c3)
        : "r"(a0), "r"(a1), "r"(a2), "r"(a3), "r"(b0), "r"(b1));
}

// ---------------- kernel 2 ----------------
__global__ void __launch_bounds__(TILE)
k_field(const float* __restrict__ pos, const float* __restrict__ dir,
        const float* __restrict__ app,
        const float* __restrict__ Wd1, const float* __restrict__ bd1,
        const float* __restrict__ Wd2, const float* __restrict__ bd2,
        const float* __restrict__ Wc1, const float* __restrict__ bc1,
        const float* __restrict__ Wc2, const float* __restrict__ bc2,
        float* __restrict__ out, int tpf)
{
    extern __shared__ float sm[];
    unsigned* smw = (unsigned*)sm;
    int* sPidx = (int*)(sm + OFF_PIDX);

    int f = blockIdx.x / tpf;
    int t = blockIdx.x - f * tpf;
    int cnt = g_counts[f];
    if (t * TILE >= cnt) return;

    int tid = threadIdx.x;

    // ---- stage weights ----
    {
        const float* g = Wd1 + f*3*HIDDEN;
        for (int i = tid; i < 3*HIDDEN; i += TILE) sm[OFF_WD1 + i] = g[i];
    }
    sm[OFF_BD1 + tid] = bd1[f*HIDDEN + tid];
    if (tid < 16) sm[OFF_BD2 + tid] = bd2[f*16 + tid];
    sm[OFF_BC1 + tid] = bc1[f*HIDDEN + tid];
    if (tid < 3) sm[OFF_BC2 + tid] = bc2[f*3 + tid];
    if (tid == 3) sm[OFF_BC2 + 3] = 0.f;
    {   // Wd2 [k=128][n=16] -> half2 words [kp=64][n=16], stride 24
        const float* g = Wd2 + f*HIDDEN*16;
        for (int i = tid; i < 64*16; i += TILE) {
            int kp = i >> 4, nn = i & 15;
            smw[OFF_WD2H + kp*WD2_STRIDE + nn] =
                packh2(g[(2*kp)*16 + nn], g[(2*kp+1)*16 + nn]);
        }
    }
    {   // Wc1 [k=50][n=128] -> half2 words [kp=32][n=128], stride 136
        const float* g = Wc1 + f*CIN*HIDDEN;
        for (int i = tid; i < 32*HIDDEN; i += TILE) {
            int kp = i >> 7, nn = i & 127;
            unsigned w = 0u;
            if (kp < 25)
                w = packh2(g[(2*kp)*HIDDEN + nn], g[(2*kp+1)*HIDDEN + nn]);
            smw[OFF_WC1 + kp*WC1_STRIDE + nn] = w;
        }
    }
    {
        const float* g = Wc2 + f*HIDDEN*3;
        sm[OFF_WC2 + tid*4+0] = g[tid*3+0];
        sm[OFF_WC2 + tid*4+1] = g[tid*3+1];
        sm[OFF_WC2 + tid*4+2] = g[tid*3+2];
        sm[OFF_WC2 + tid*4+3] = 0.f;
    }
    __syncthreads();

    // ---- scalar L1: h = relu(pos@Wd1 + bd1), pack fp16, store to smem ----
    int bi = t * TILE + tid;
    bool valid = (bi < cnt);
    int p = g_bucket[f][valid ? bi : (cnt - 1)];
    sPidx[tid] = valid ? p : -1;

    float px = pos[3*p], py = pos[3*p+1], pz = pos[3*p+2];
    {
        uint4* hrow = (uint4*)(smw + OFF_H + tid*H_STRIDE);
        #pragma unroll
        for (int j = 0; j < HIDDEN; j += 8) {
            unsigned w[2];
            #pragma unroll
            for (int u = 0; u < 8; u += 2) {
                float4 wx = *(const float4*)&sm[OFF_WD1 + 0*HIDDEN + j + u - (j+u & 3)];
                // (recompute per element to keep it simple & correct)
                float h0, h1;
                {
                    int jj = j + u;
                    float a0 = sm[OFF_WD1 + 0*HIDDEN + jj], a1 = sm[OFF_WD1 + 0*HIDDEN + jj+1];
                    float b0 = sm[OFF_WD1 + 1*HIDDEN + jj], b1 = sm[OFF_WD1 + 1*HIDDEN + jj+1];
                    float c0 = sm[OFF_WD1 + 2*HIDDEN + jj], c1 = sm[OFF_WD1 + 2*HIDDEN + jj+1];
                    float d0 = sm[OFF_BD1 + jj],            d1 = sm[OFF_BD1 + jj+1];
                    h0 = fmaxf(fmaf(px,a0,fmaf(py,b0,fmaf(pz,c0,d0))), 0.f);
                    h1 = fmaxf(fmaf(px,a1,fmaf(py,b1,fmaf(pz,c1,d1))), 0.f);
                }
                w[u>>2 ? 1 : (u>>1)&1 ? 1 : 0] = 0; // dummy, replaced below
                (void)wx;
                if ((u & 3) == 0) w[0] = packh2(h0, h1);
                else              w[1] = packh2(h0, h1);
                if ((u & 3) == 2) {
                    // store pair later
                }
            }
            // The above got convoluted; fall through to simple path below.
            (void)w; (void)hrow;
            break;
        }
        // ---- simple correct path: compute 8 h at a time, one uint4 store ----
        #pragma unroll
        for (int j = 0; j < HIDDEN; j += 8) {
            float hv[8];
            #pragma unroll
            for (int u = 0; u < 8; u++) {
                int jj = j + u;
                hv[u] = fmaxf(fmaf(px, sm[OFF_WD1 + 0*HIDDEN + jj],
                              fmaf(py, sm[OFF_WD1 + 1*HIDDEN + jj],
                              fmaf(pz, sm[OFF_WD1 + 2*HIDDEN + jj],
                                   sm[OFF_BD1 + jj]))), 0.f);
            }
            hrow[j >> 3] = make_uint4(packh2(hv[0],hv[1]), packh2(hv[2],hv[3]),
                                      packh2(hv[4],hv[5]), packh2(hv[6],hv[7]));
        }
    }
    __syncwarp();

    int lane = tid & 31;
    int wid  = tid >> 5;
    int g    = lane >> 2;
    int tg   = lane & 3;
    int wbase = wid * 32;

    const unsigned* H32  = smw + OFF_H;
    const unsigned* WD2w = smw + OFF_WD2H;
    const unsigned* W32  = smw + OFF_WC1;
    const float4*  WC2v  = (const float4*)(sm + OFF_WC2);
    float* D0S = sm + OFF_D0S;

    // ---- L2 MMA: D0 = h @ Wd2 (M=32/warp-tile x N=16 x K=128) ----
    #pragma unroll
    for (int mt = 0; mt < 2; mt++) {
        int r0 = wbase + 16*mt + g;
        unsigned ah[8][4];
        #pragma unroll
        for (int ks = 0; ks < 8; ks++) {
            int c = 8*ks + tg;
            ah[ks][0] = H32[(r0    )*H_STRIDE + c    ];
            ah[ks][1] = H32[(r0 + 8)*H_STRIDE + c    ];
            ah[ks][2] = H32[(r0    )*H_STRIDE + c + 4];
            ah[ks][3] = H32[(r0 + 8)*H_STRIDE + c + 4];
        }
        #pragma unroll
        for (int nt = 0; nt < 2; nt++) {
            int coln = 8*nt + g;
            float cA0=0.f,cA1=0.f,cA2=0.f,cA3=0.f;
            float cB0=0.f,cB1=0.f,cB2=0.f,cB3=0.f;
            #pragma unroll
            for (int ks = 0; ks < 8; ks += 2) {
                unsigned b00 = WD2w[(8*ks + tg    )*WD2_STRIDE + coln];
                unsigned b01 = WD2w[(8*ks + tg + 4)*WD2_STRIDE + coln];
                unsigned b10 = WD2w[(8*(ks+1) + tg    )*WD2_STRIDE + coln];
                unsigned b11 = WD2w[(8*(ks+1) + tg + 4)*WD2_STRIDE + coln];
                mma_f16(cA0,cA1,cA2,cA3, ah[ks][0],ah[ks][1],ah[ks][2],ah[ks][3], b00,b01);
                mma_f16(cB0,cB1,cB2,cB3, ah[ks+1][0],ah[ks+1][1],ah[ks+1][2],ah[ks+1][3], b10,b11);
            }
            int cbase = 8*nt + 2*tg;
            float* rA = D0S + (size_t)(r0    )*D0_STRIDE + cbase;
            float* rB = D0S + (size_t)(r0 + 8)*D0_STRIDE + cbase;
            rA[0] = cA0 + cB0;  rA[1] = cA1 + cB1;
            rB[0] = cA2 + cB2;  rB[1] = cA3 + cB3;
        }
    }
    __syncwarp();

    // ---- readback d0 (own row), density out, build CIN over H region ----
    {
        float d0[16];
        const float4* drow = (const float4*)(D0S + (size_t)tid*D0_STRIDE);
        #pragma unroll
        for (int q = 0; q < 4; q++) {
            float4 v = drow[q];
            d0[4*q+0] = v.x + sm[OFF_BD2 + 4*q+0];
            d0[4*q+1] = v.y + sm[OFF_BD2 + 4*q+1];
            d0[4*q+2] = v.z + sm[OFF_BD2 + 4*q+2];
            d0[4*q+3] = v.w + sm[OFF_BD2 + 4*q+3];
        }
        if (valid) out[(size_t)4*p] = expf(d0[0]);

        float cv[56];
        cv[0] = dir[3*p]; cv[1] = dir[3*p+1]; cv[2] = dir[3*p+2];
        #pragma unroll
        for (int g2 = 0; g2 < GEO; g2++) cv[3+g2] = d0[1+g2];
        const float4* ap = (const float4*)(app + (size_t)p*APP);
        #pragma unroll
        for (int q = 0; q < APP/4; q++) {
            float4 v = __ldg(&ap[q]);
            cv[18+4*q+0] = v.x; cv[18+4*q+1] = v.y;
            cv[18+4*q+2] = v.z; cv[18+4*q+3] = v.w;
        }
        #pragma unroll
        for (int c = CIN; c < 56; c++) cv[c] = 0.f;
        unsigned w[32];
        #pragma unroll
        for (int q = 0; q < 28; q++) w[q] = packh2(cv[2*q], cv[2*q+1]);
        #pragma unroll
        for (int q = 28; q < 32; q++) w[q] = 0u;
        uint4* row = (uint4*)(smw + OFF_H + tid*H_STRIDE);  // reuse h region
        #pragma unroll
        for (int q = 0; q < 8; q++)
            row[q] = make_uint4(w[4*q], w[4*q+1], w[4*q+2], w[4*q+3]);
    }
    __syncwarp();

    // ---- color MMA: HC = relu(CIN @ Wc1 + bc1); RGB = HC @ Wc2 fused ----
    unsigned a[2][4][4];
    #pragma unroll
    for (int mt = 0; mt < 2; mt++) {
        int r0 = wbase + 16*mt + g;
        #pragma unroll
        for (int ks = 0; ks < 4; ks++) {
            int c = 8*ks + tg;
            a[mt][ks][0] = H32[(r0    )*H_STRIDE + c    ];
            a[mt][ks][1] = H32[(r0 + 8)*H_STRIDE + c    ];
            a[mt][ks][2] = H32[(r0    )*H_STRIDE + c + 4];
            a[mt][ks][3] = H32[(r0 + 8)*H_STRIDE + c + 4];
        }
    }

    float acc[4][3];
    #pragma unroll
    for (int q = 0; q < 4; q++) { acc[q][0]=0.f; acc[q][1]=0.f; acc[q][2]=0.f; }

    #pragma unroll 2
    for (int nb = 0; nb < 16; nb++) {
        int coln = 8*nb + g;
        unsigned b[4][2];
        #pragma unroll
        for (int ks = 0; ks < 4; ks++) {
            b[ks][0] = W32[(8*ks + tg    )*WC1_STRIDE + coln];
            b[ks][1] = W32[(8*ks + tg + 4)*WC1_STRIDE + coln];
        }
        int j0 = 8*nb + 2*tg;
        float bj0 = sm[OFF_BC1 + j0], bj1 = sm[OFF_BC1 + j0 + 1];
        float4 w0 = WC2v[j0];
        float4 w1 = WC2v[j0 + 1];

        #pragma unroll
        for (int mt = 0; mt < 2; mt++) {
            float cA0=0.f,cA1=0.f,cA2=0.f,cA3=0.f;
            float cB0=0.f,cB1=0.f,cB2=0.f,cB3=0.f;
            mma_f16(cA0,cA1,cA2,cA3, a[mt][0][0],a[mt][0][1],a[mt][0][2],a[mt][0][3], b[0][0],b[0][1]);
            mma_f16(cB0,cB1,cB2,cB3, a[mt][1][0],a[mt][1][1],a[mt][1][2],a[mt][1][3], b[1][0],b[1][1]);
            mma_f16(cA0,cA1,cA2,cA3, a[mt][2][0],a[mt][2][1],a[mt][2][2],a[mt][2][3], b[2][0],b[2][1]);
            mma_f16(cB0,cB1,cB2,cB3, a[mt][3][0],a[mt][3][1],a[mt][3][2],a[mt][3][3], b[3][0],b[3][1]);
            float h00 = fmaxf(cA0 + cB0 + bj0, 0.f);
            float h01 = fmaxf(cA1 + cB1 + bj1, 0.f);
            float h10 = fmaxf(cA2 + cB2 + bj0, 0.f);
            float h11 = fmaxf(cA3 + cB3 + bj1, 0.f);
            int q0 = 2*mt, q1 = 2*mt + 1;
            acc[q0][0] = fmaf(h00, w0.x, fmaf(h01, w1.x, acc[q0][0]));
            acc[q0][1] = fmaf(h00, w0.y, fmaf(h01, w1.y, acc[q0][1]));
            acc[q0][2] = fmaf(h00, w0.z, fmaf(h01, w1.z, acc[q0][2]));
            acc[q1][0] = fmaf(h10, w0.x, fmaf(h11, w1.x, acc[q1][0]));
            acc[q1][1] = fmaf(h10, w0.y, fmaf(h11, w1.y, acc[q1][1]));
            acc[q1][2] = fmaf(h10, w0.z, fmaf(h11, w1.z, acc[q1][2]));
        }
    }

    #pragma unroll
    for (int q = 0; q < 4; q++)
        #pragma unroll
        for (int c = 0; c < 3; c++) {
            float v = acc[q][c];
            v += __shfl_xor_sync(0xffffffffu, v, 1);
            v += __shfl_xor_sync(0xffffffffu, v, 2);
            acc[q][c] = v;
        }

    {
        int row = wbase + g + 8*tg;
        float r0 = acc[tg][0], r1 = acc[tg][1], r2 = acc[tg][2];
        int pp = sPidx[row];
        if (pp >= 0) {
            r0 += sm[OFF_BC2 + 0];
            r1 += sm[OFF_BC2 + 1];
            r2 += sm[OFF_BC2 + 2];
            out[(size_t)4*pp + 1] = 1.f / (1.f + expf(-r0));
            out[(size_t)4*pp + 2] = 1.f / (1.f + expf(-r1));
            out[(size_t)4*pp + 3] = 1.f / (1.f + expf(-r2));
        }
    }
}

// ---------------- launch ----------------
extern "C" void kernel_launch(void* const* d_in, const int* in_sizes, int n_in,
                              void* d_out, int out_size) {
    const float* positions  = (const float*)d_in[0];
    const float* directions = (const float*)d_in[1];
    const float* appearance = (const float*)d_in[2];
    const float* centroids  = (const float*)d_in[3];
    const float* Wd1 = (const float*)d_in[4];
    const float* bd1 = (const float*)d_in[5];
    const float* Wd2 = (const float*)d_in[6];
    const float* bd2 = (const float*)d_in[7];
    const float* Wc1 = (const float*)d_in[8];
    const float* bc1 = (const float*)d_in[9];
    const float* Wc2 = (const float*)d_in[10];
    const float* bc2 = (const float*)d_in[11];
    float* out = (float*)d_out;

    int n = in_sizes[0] / 3;
    if (n > N_MAX) n = N_MAX;
    int tpf = (n + TILE - 1) / TILE;

    cudaFuncSetAttribute(k_field, cudaFuncAttributeMaxDynamicSharedMemorySize,
                         SMEM_BYTES);

    k_zero<<<1, 32>>>();
    k_assign<<<(n + 255) / 256, 256>>>(positions, centroids, n);
    k_field<<<N_FIELDS * tpf, TILE, SMEM_BYTES>>>(positions, directions, appearance,
                                                  Wd1, bd1, Wd2, bd2, Wc1, bc1,
                                                  Wc2, bc2, out, tpf);
}

// round 8
// speedup vs baseline: 3.0953x; 1.2796x over previous
#include <cuda_runtime.h>
#include <cuda_fp16.h>
#include <math.h>

#define N_FIELDS 8
#define HIDDEN   128
#define GEO      15
#define APP      32
#define CIN      50
#define N_MAX    524288
#define TILE     128
#define TILES_PER_BLOCK 8
#define PTS_PER_BLOCK   (TILE * TILES_PER_BLOCK)

#define H_STRIDE   68    // u32 words/row (h/cin fp16)
#define WD2_STRIDE 24
#define WC1_STRIDE 136   // 136 mod 32 = 8 -> conflict-free B-frags
#define D0_STRIDE  20    // fp32 scratch; float4 readback conflict-free

// ---- dynamic smem layout (32-bit word offsets) ----
#define OFF_WD1    0       // 384
#define OFF_BD1    384     // 128
#define OFF_BD2    512     // 16
#define OFF_BC1    528     // 128
#define OFF_BC2    656     // 4
#define OFF_WC2    660     // 512 (float4[128]); byte 2640, 16B aligned
#define OFF_WD2H   1172    // 64*24 = 1536 (half2 of Wd2)
#define OFF_WC1    2708    // 32*136 = 4352 (half2 of Wc1)
#define OFF_H      7060    // 128*68 = 8704 (h fp16; reused for CIN) byte 28240, 16B aligned
#define OFF_D0S    15764   // 128*20 = 2560 (fp32 d0 scratch) byte 63056, 16B aligned
#define SMEM_WORDS 18324
#define SMEM_BYTES (SMEM_WORDS * 4)

// ---------------- device scratch ----------------
__device__ int g_counts[N_FIELDS];
__device__ int g_bucket[N_FIELDS][N_MAX];

__global__ void k_zero() {
    if (threadIdx.x < N_FIELDS) g_counts[threadIdx.x] = 0;
}

__global__ void k_assign(const float* __restrict__ pos,
                         const float* __restrict__ cent, int n) {
    int i = blockIdx.x * blockDim.x + threadIdx.x;
    unsigned act = __ballot_sync(0xffffffffu, i < n);
    if (i >= n) return;
    float px = pos[3*i], py = pos[3*i+1], pz = pos[3*i+2];
    int best = 0; float bd = 3.402823e38f;
    #pragma unroll
    for (int c = 0; c < N_FIELDS; c++) {
        float dx = px - __ldg(&cent[3*c+0]);
        float dy = py - __ldg(&cent[3*c+1]);
        float dz = pz - __ldg(&cent[3*c+2]);
        float d = dx*dx + dy*dy + dz*dz;
        if (d < bd) { bd = d; best = c; }
    }
    unsigned peers  = __match_any_sync(act, best);
    int leader = __ffs(peers) - 1;
    int lane   = threadIdx.x & 31;
    int base = 0;
    if (lane == leader) base = atomicAdd(&g_counts[best], __popc(peers));
    base = __shfl_sync(peers, base, leader);
    g_bucket[best][base + __popc(peers & ((1u << lane) - 1u))] = i;
}

// ---- helpers ----
__device__ __forceinline__ unsigned packh2(float lo, float hi) {
    __half2 h = __floats2half2_rn(lo, hi);
    return *(unsigned*)&h;
}
__device__ __forceinline__ void mma_f16(float& c0, float& c1, float& c2, float& c3,
                                        unsigned a0, unsigned a1, unsigned a2, unsigned a3,
                                        unsigned b0, unsigned b1) {
    asm("mma.sync.aligned.m16n8k16.row.col.f32.f16.f16.f32 "
        "{%0,%1,%2,%3},{%4,%5,%6,%7},{%8,%9},{%0,%1,%2,%3};"
        : "+f"(c0), "+f"(c1), "+f"(c2), "+f"(c3)
        : "r"(a0), "r"(a1), "r"(a2), "r"(a3), "r"(b0), "r"(b1));
}

// ---------------- kernel 2 ----------------
__global__ void __launch_bounds__(TILE)
k_field(const float* __restrict__ pos, const float* __restrict__ dir,
        const float* __restrict__ app,
        const float* __restrict__ Wd1, const float* __restrict__ bd1,
        const float* __restrict__ Wd2, const float* __restrict__ bd2,
        const float* __restrict__ Wc1, const float* __restrict__ bc1,
        const float* __restrict__ Wc2, const float* __restrict__ bc2,
        float* __restrict__ out, int tpf)
{
    extern __shared__ float sm[];
    unsigned* smw = (unsigned*)sm;

    int f = blockIdx.x / tpf;
    int t = blockIdx.x - f * tpf;
    int cnt = g_counts[f];
    if (t * PTS_PER_BLOCK >= cnt) return;

    int tid = threadIdx.x;

    // ---- stage weights (once per block, amortized over 8 tiles) ----
    {
        const float* g = Wd1 + f*3*HIDDEN;
        for (int i = tid; i < 3*HIDDEN; i += TILE) sm[OFF_WD1 + i] = g[i];
    }
    sm[OFF_BD1 + tid] = bd1[f*HIDDEN + tid];
    if (tid < 16) sm[OFF_BD2 + tid] = bd2[f*16 + tid];
    sm[OFF_BC1 + tid] = bc1[f*HIDDEN + tid];
    if (tid < 3) sm[OFF_BC2 + tid] = bc2[f*3 + tid];
    if (tid == 3) sm[OFF_BC2 + 3] = 0.f;
    {   // Wd2 [k=128][n=16] -> half2 [kp=64][n=16], stride 24
        const float* g = Wd2 + f*HIDDEN*16;
        for (int i = tid; i < 64*16; i += TILE) {
            int kp = i >> 4, nn = i & 15;
            smw[OFF_WD2H + kp*WD2_STRIDE + nn] =
                packh2(g[(2*kp)*16 + nn], g[(2*kp+1)*16 + nn]);
        }
    }
    {   // Wc1 [k=50][n=128] -> half2 [kp=32][n=128], stride 136
        const float* g = Wc1 + f*CIN*HIDDEN;
        for (int i = tid; i < 32*HIDDEN; i += TILE) {
            int kp = i >> 7, nn = i & 127;
            unsigned w = 0u;
            if (kp < 25)
                w = packh2(g[(2*kp)*HIDDEN + nn], g[(2*kp+1)*HIDDEN + nn]);
            smw[OFF_WC1 + kp*WC1_STRIDE + nn] = w;
        }
    }
    {
        const float* g = Wc2 + f*HIDDEN*3;
        sm[OFF_WC2 + tid*4+0] = g[tid*3+0];
        sm[OFF_WC2 + tid*4+1] = g[tid*3+1];
        sm[OFF_WC2 + tid*4+2] = g[tid*3+2];
        sm[OFF_WC2 + tid*4+3] = 0.f;
    }
    __syncthreads();

    int lane = tid & 31;
    int wid  = tid >> 5;
    int g    = lane >> 2;
    int tg   = lane & 3;
    int wbase = wid * 32;

    const unsigned* H32  = smw + OFF_H;
    const unsigned* WD2w = smw + OFF_WD2H;
    const unsigned* W32  = smw + OFF_WC1;
    const float4*  WC2v  = (const float4*)(sm + OFF_WC2);
    float* D0S = sm + OFF_D0S;

    // ---- tile loop: all smem rows used below are warp-private ----
    for (int tile = 0; tile < TILES_PER_BLOCK; tile++) {
        int base = t * PTS_PER_BLOCK + tile * TILE;
        if (base >= cnt) break;
        int bi = base + tid;
        bool valid = (bi < cnt);
        int p = g_bucket[f][valid ? bi : (cnt - 1)];

        // ---- scalar L1: h = relu(pos@Wd1 + bd1) -> fp16 smem ----
        float px = pos[3*p], py = pos[3*p+1], pz = pos[3*p+2];
        {
            uint4* hrow = (uint4*)(smw + OFF_H + tid*H_STRIDE);
            #pragma unroll
            for (int j = 0; j < HIDDEN; j += 8) {
                float hv[8];
                #pragma unroll
                for (int u = 0; u < 8; u++) {
                    int jj = j + u;
                    hv[u] = fmaxf(fmaf(px, sm[OFF_WD1 + 0*HIDDEN + jj],
                                  fmaf(py, sm[OFF_WD1 + 1*HIDDEN + jj],
                                  fmaf(pz, sm[OFF_WD1 + 2*HIDDEN + jj],
                                       sm[OFF_BD1 + jj]))), 0.f);
                }
                hrow[j >> 3] = make_uint4(packh2(hv[0],hv[1]), packh2(hv[2],hv[3]),
                                          packh2(hv[4],hv[5]), packh2(hv[6],hv[7]));
            }
        }
        __syncwarp();

        // ---- L2 MMA: D0 = h @ Wd2 (M=32 x N=16 x K=128 per warp) ----
        #pragma unroll
        for (int mt = 0; mt < 2; mt++) {
            int r0 = wbase + 16*mt + g;
            unsigned ah[8][4];
            #pragma unroll
            for (int ks = 0; ks < 8; ks++) {
                int c = 8*ks + tg;
                ah[ks][0] = H32[(r0    )*H_STRIDE + c    ];
                ah[ks][1] = H32[(r0 + 8)*H_STRIDE + c    ];
                ah[ks][2] = H32[(r0    )*H_STRIDE + c + 4];
                ah[ks][3] = H32[(r0 + 8)*H_STRIDE + c + 4];
            }
            #pragma unroll
            for (int nt = 0; nt < 2; nt++) {
                int coln = 8*nt + g;
                float cA0=0.f,cA1=0.f,cA2=0.f,cA3=0.f;
                float cB0=0.f,cB1=0.f,cB2=0.f,cB3=0.f;
                #pragma unroll
                for (int ks = 0; ks < 8; ks += 2) {
                    unsigned b00 = WD2w[(8*ks + tg    )*WD2_STRIDE + coln];
                    unsigned b01 = WD2w[(8*ks + tg + 4)*WD2_STRIDE + coln];
                    unsigned b10 = WD2w[(8*(ks+1) + tg    )*WD2_STRIDE + coln];
                    unsigned b11 = WD2w[(8*(ks+1) + tg + 4)*WD2_STRIDE + coln];
                    mma_f16(cA0,cA1,cA2,cA3, ah[ks][0],ah[ks][1],ah[ks][2],ah[ks][3], b00,b01);
                    mma_f16(cB0,cB1,cB2,cB3, ah[ks+1][0],ah[ks+1][1],ah[ks+1][2],ah[ks+1][3], b10,b11);
                }
                int cbase = 8*nt + 2*tg;
                float* rA = D0S + (size_t)(r0    )*D0_STRIDE + cbase;
                float* rB = D0S + (size_t)(r0 + 8)*D0_STRIDE + cbase;
                rA[0] = cA0 + cB0;  rA[1] = cA1 + cB1;
                rB[0] = cA2 + cB2;  rB[1] = cA3 + cB3;
            }
        }
        __syncwarp();

        // ---- readback d0, density out, build CIN over H region ----
        {
            float d0[16];
            const float4* drow = (const float4*)(D0S + (size_t)tid*D0_STRIDE);
            #pragma unroll
            for (int q = 0; q < 4; q++) {
                float4 v = drow[q];
                d0[4*q+0] = v.x + sm[OFF_BD2 + 4*q+0];
                d0[4*q+1] = v.y + sm[OFF_BD2 + 4*q+1];
                d0[4*q+2] = v.z + sm[OFF_BD2 + 4*q+2];
                d0[4*q+3] = v.w + sm[OFF_BD2 + 4*q+3];
            }
            if (valid) out[(size_t)4*p] = expf(d0[0]);

            float cv[56];
            cv[0] = dir[3*p]; cv[1] = dir[3*p+1]; cv[2] = dir[3*p+2];
            #pragma unroll
            for (int g2 = 0; g2 < GEO; g2++) cv[3+g2] = d0[1+g2];
            const float4* ap = (const float4*)(app + (size_t)p*APP);
            #pragma unroll
            for (int q = 0; q < APP/4; q++) {
                float4 v = __ldg(&ap[q]);
                cv[18+4*q+0] = v.x; cv[18+4*q+1] = v.y;
                cv[18+4*q+2] = v.z; cv[18+4*q+3] = v.w;
            }
            #pragma unroll
            for (int c = CIN; c < 56; c++) cv[c] = 0.f;
            unsigned w[32];
            #pragma unroll
            for (int q = 0; q < 28; q++) w[q] = packh2(cv[2*q], cv[2*q+1]);
            #pragma unroll
            for (int q = 28; q < 32; q++) w[q] = 0u;
            uint4* row = (uint4*)(smw + OFF_H + tid*H_STRIDE);  // reuse h region
            #pragma unroll
            for (int q = 0; q < 8; q++)
                row[q] = make_uint4(w[4*q], w[4*q+1], w[4*q+2], w[4*q+3]);
        }
        __syncwarp();

        // ---- color MMA: HC = relu(CIN @ Wc1 + bc1); RGB = HC @ Wc2 fused ----
        unsigned a[2][4][4];
        #pragma unroll
        for (int mt = 0; mt < 2; mt++) {
            int r0 = wbase + 16*mt + g;
            #pragma unroll
            for (int ks = 0; ks < 4; ks++) {
                int c = 8*ks + tg;
                a[mt][ks][0] = H32[(r0    )*H_STRIDE + c    ];
                a[mt][ks][1] = H32[(r0 + 8)*H_STRIDE + c    ];
                a[mt][ks][2] = H32[(r0    )*H_STRIDE + c + 4];
                a[mt][ks][3] = H32[(r0 + 8)*H_STRIDE + c + 4];
            }
        }

        float acc[4][3];
        #pragma unroll
        for (int q = 0; q < 4; q++) { acc[q][0]=0.f; acc[q][1]=0.f; acc[q][2]=0.f; }

        #pragma unroll 2
        for (int nb = 0; nb < 16; nb++) {
            int coln = 8*nb + g;
            unsigned b[4][2];
            #pragma unroll
            for (int ks = 0; ks < 4; ks++) {
                b[ks][0] = W32[(8*ks + tg    )*WC1_STRIDE + coln];
                b[ks][1] = W32[(8*ks + tg + 4)*WC1_STRIDE + coln];
            }
            int j0 = 8*nb + 2*tg;
            float bj0 = sm[OFF_BC1 + j0], bj1 = sm[OFF_BC1 + j0 + 1];
            float4 w0 = WC2v[j0];
            float4 w1 = WC2v[j0 + 1];

            #pragma unroll
            for (int mt = 0; mt < 2; mt++) {
                float cA0=0.f,cA1=0.f,cA2=0.f,cA3=0.f;
                float cB0=0.f,cB1=0.f,cB2=0.f,cB3=0.f;
                mma_f16(cA0,cA1,cA2,cA3, a[mt][0][0],a[mt][0][1],a[mt][0][2],a[mt][0][3], b[0][0],b[0][1]);
                mma_f16(cB0,cB1,cB2,cB3, a[mt][1][0],a[mt][1][1],a[mt][1][2],a[mt][1][3], b[1][0],b[1][1]);
                mma_f16(cA0,cA1,cA2,cA3, a[mt][2][0],a[mt][2][1],a[mt][2][2],a[mt][2][3], b[2][0],b[2][1]);
                mma_f16(cB0,cB1,cB2,cB3, a[mt][3][0],a[mt][3][1],a[mt][3][2],a[mt][3][3], b[3][0],b[3][1]);
                float h00 = fmaxf(cA0 + cB0 + bj0, 0.f);
                float h01 = fmaxf(cA1 + cB1 + bj1, 0.f);
                float h10 = fmaxf(cA2 + cB2 + bj0, 0.f);
                float h11 = fmaxf(cA3 + cB3 + bj1, 0.f);
                int q0 = 2*mt, q1 = 2*mt + 1;
                acc[q0][0] = fmaf(h00, w0.x, fmaf(h01, w1.x, acc[q0][0]));
                acc[q0][1] = fmaf(h00, w0.y, fmaf(h01, w1.y, acc[q0][1]));
                acc[q0][2] = fmaf(h00, w0.z, fmaf(h01, w1.z, acc[q0][2]));
                acc[q1][0] = fmaf(h10, w0.x, fmaf(h11, w1.x, acc[q1][0]));
                acc[q1][1] = fmaf(h10, w0.y, fmaf(h11, w1.y, acc[q1][1]));
                acc[q1][2] = fmaf(h10, w0.z, fmaf(h11, w1.z, acc[q1][2]));
            }
        }

        #pragma unroll
        for (int q = 0; q < 4; q++)
            #pragma unroll
            for (int c = 0; c < 3; c++) {
                float v = acc[q][c];
                v += __shfl_xor_sync(0xffffffffu, v, 1);
                v += __shfl_xor_sync(0xffffffffu, v, 2);
                acc[q][c] = v;
            }

        {
            int row = wbase + g + 8*tg;       // this thread writes that row's rgb
            int bi2 = base + row;
            if (bi2 < cnt) {
                int pp = g_bucket[f][bi2];
                float r0 = acc[tg][0] + sm[OFF_BC2 + 0];
                float r1 = acc[tg][1] + sm[OFF_BC2 + 1];
                float r2 = acc[tg][2] + sm[OFF_BC2 + 2];
                out[(size_t)4*pp + 1] = 1.f / (1.f + expf(-r0));
                out[(size_t)4*pp + 2] = 1.f / (1.f + expf(-r1));
                out[(size_t)4*pp + 3] = 1.f / (1.f + expf(-r2));
            }
        }
        __syncwarp();   // protect H region reuse next tile
    }
}

// ---------------- launch ----------------
extern "C" void kernel_launch(void* const* d_in, const int* in_sizes, int n_in,
                              void* d_out, int out_size) {
    const float* positions  = (const float*)d_in[0];
    const float* directions = (const float*)d_in[1];
    const float* appearance = (const float*)d_in[2];
    const float* centroids  = (const float*)d_in[3];
    const float* Wd1 = (const float*)d_in[4];
    const float* bd1 = (const float*)d_in[5];
    const float* Wd2 = (const float*)d_in[6];
    const float* bd2 = (const float*)d_in[7];
    const float* Wc1 = (const float*)d_in[8];
    const float* bc1 = (const float*)d_in[9];
    const float* Wc2 = (const float*)d_in[10];
    const float* bc2 = (const float*)d_in[11];
    float* out = (float*)d_out;

    int n = in_sizes[0] / 3;
    if (n > N_MAX) n = N_MAX;
    int tpf = (n + PTS_PER_BLOCK - 1) / PTS_PER_BLOCK;

    cudaFuncSetAttribute(k_field, cudaFuncAttributeMaxDynamicSharedMemorySize,
                         SMEM_BYTES);

    k_zero<<<1, 32>>>();
    k_assign<<<(n + 255) / 256, 256>>>(positions, centroids, n);
    k_field<<<N_FIELDS * tpf, TILE, SMEM_BYTES>>>(positions, directions, appearance,
                                                  Wd1, bd1, Wd2, bd2, Wc1, bc1,
                                                  Wc2, bc2, out, tpf);
}

// round 10
// speedup vs baseline: 3.6634x; 1.1835x over previous
#include <cuda_runtime.h>
#include <cuda_fp16.h>
#include <math.h>

#define N_FIELDS 8
#define HIDDEN   128
#define GEO      15
#define APP      32
#define CIN      50
#define N_MAX    524288
#define TILE     128
#define TILES_PER_BLOCK 8
#define PTS_PER_BLOCK   1024

#define H_STRIDE   36    // u32 words/row: 32 data + 4 pad; 36%32=4 -> conflict-free
#define WD2_STRIDE 24
#define WC1_STRIDE 136   // 136%32=8 -> conflict-free B-frags

// ---- dynamic smem layout (32-bit word offsets) ----
#define OFF_WD1    0       // 384
#define OFF_BD1    384     // 128
#define OFF_BD2    512     // 16
#define OFF_BC1    528     // 128
#define OFF_BC2    656     // 4
#define OFF_WC2    660     // 512 (float4[128]); byte 2640, 16B aligned
#define OFF_WD2H   1172    // 64*24 = 1536 (half2 of Wd2)
#define OFF_WC1    2708    // 32*136 = 4352 (half2 of Wc1)
#define OFF_H      7060    // 128*36 = 4608; byte 28240, 16B aligned (144B rows)
#define SMEM_WORDS 11668
#define SMEM_BYTES (SMEM_WORDS * 4)   // 46672 B -> 4 blocks/SM

// ---------------- device scratch ----------------
__device__ int g_counts[N_FIELDS];
__device__ int g_bucket[N_FIELDS][N_MAX];

__global__ void k_assign(const float* __restrict__ pos,
                         const float* __restrict__ cent, int n) {
    int i = blockIdx.x * blockDim.x + threadIdx.x;
    unsigned act = __ballot_sync(0xffffffffu, i < n);
    if (i >= n) return;
    float px = pos[3*i], py = pos[3*i+1], pz = pos[3*i+2];
    int best = 0; float bd = 3.402823e38f;
    #pragma unroll
    for (int c = 0; c < N_FIELDS; c++) {
        float dx = px - __ldg(&cent[3*c+0]);
        float dy = py - __ldg(&cent[3*c+1]);
        float dz = pz - __ldg(&cent[3*c+2]);
        float d = dx*dx + dy*dy + dz*dz;
        if (d < bd) { bd = d; best = c; }
    }
    unsigned peers  = __match_any_sync(act, best);
    int leader = __ffs(peers) - 1;
    int lane   = threadIdx.x & 31;
    int base = 0;
    if (lane == leader) base = atomicAdd(&g_counts[best], __popc(peers));
    base = __shfl_sync(peers, base, leader);
    g_bucket[best][base + __popc(peers & ((1u << lane) - 1u))] = i;
}

// ---- helpers ----
__device__ __forceinline__ unsigned packh2(float lo, float hi) {
    __half2 h = __floats2half2_rn(lo, hi);
    return *(unsigned*)&h;
}
__device__ __forceinline__ void mma_f16(float& c0, float& c1, float& c2, float& c3,
                                        unsigned a0, unsigned a1, unsigned a2, unsigned a3,
                                        unsigned b0, unsigned b1) {
    asm("mma.sync.aligned.m16n8k16.row.col.f32.f16.f16.f32 "
        "{%0,%1,%2,%3},{%4,%5,%6,%7},{%8,%9},{%0,%1,%2,%3};"
        : "+f"(c0), "+f"(c1), "+f"(c2), "+f"(c3)
        : "r"(a0), "r"(a1), "r"(a2), "r"(a3), "r"(b0), "r"(b1));
}

// ---------------- kernel 2 ----------------
__global__ void __launch_bounds__(TILE, 4)
k_field(const float* __restrict__ pos, const float* __restrict__ dir,
        const float* __restrict__ app,
        const float* __restrict__ Wd1, const float* __restrict__ bd1,
        const float* __restrict__ Wd2, const float* __restrict__ bd2,
        const float* __restrict__ Wc1, const float* __restrict__ bc1,
        const float* __restrict__ Wc2, const float* __restrict__ bc2,
        float* __restrict__ out, int tpf)
{
    extern __shared__ float sm[];
    unsigned* smw = (unsigned*)sm;

    int f = blockIdx.x / tpf;
    int t = blockIdx.x - f * tpf;
    int cnt = g_counts[f];
    if (t * PTS_PER_BLOCK >= cnt) return;

    int tid = threadIdx.x;

    // ---- stage weights (once per block) ----
    {
        const float* g = Wd1 + f*3*HIDDEN;
        for (int i = tid; i < 3*HIDDEN; i += TILE) sm[OFF_WD1 + i] = g[i];
    }
    sm[OFF_BD1 + tid] = bd1[f*HIDDEN + tid];
    if (tid < 16) sm[OFF_BD2 + tid] = bd2[f*16 + tid];
    sm[OFF_BC1 + tid] = bc1[f*HIDDEN + tid];
    if (tid < 3) sm[OFF_BC2 + tid] = bc2[f*3 + tid];
    if (tid == 3) sm[OFF_BC2 + 3] = 0.f;
    {   // Wd2 [k=128][n=16] -> half2 [kp=64][n=16], stride 24
        const float* g = Wd2 + f*HIDDEN*16;
        for (int i = tid; i < 64*16; i += TILE) {
            int kp = i >> 4, nn = i & 15;
            smw[OFF_WD2H + kp*WD2_STRIDE + nn] =
                packh2(g[(2*kp)*16 + nn], g[(2*kp+1)*16 + nn]);
        }
    }
    {   // Wc1 [k=50][n=128] -> half2 [kp=32][n=128], stride 136 (k padded to 64)
        const float* g = Wc1 + f*CIN*HIDDEN;
        for (int i = tid; i < 32*HIDDEN; i += TILE) {
            int kp = i >> 7, nn = i & 127;
            unsigned w = 0u;
            if (kp < 25)
                w = packh2(g[(2*kp)*HIDDEN + nn], g[(2*kp+1)*HIDDEN + nn]);
            smw[OFF_WC1 + kp*WC1_STRIDE + nn] = w;
        }
    }
    {
        const float* g = Wc2 + f*HIDDEN*3;
        sm[OFF_WC2 + tid*4+0] = g[tid*3+0];
        sm[OFF_WC2 + tid*4+1] = g[tid*3+1];
        sm[OFF_WC2 + tid*4+2] = g[tid*3+2];
        sm[OFF_WC2 + tid*4+3] = 0.f;
    }
    __syncthreads();

    int lane = tid & 31;
    int wid  = tid >> 5;
    int g    = lane >> 2;
    int tg   = lane & 3;
    int wbase = wid * 32;

    const unsigned* H32  = smw + OFF_H;
    const unsigned* WD2w = smw + OFF_WD2H;
    const unsigned* W32  = smw + OFF_WC1;
    const float4*  WC2v  = (const float4*)(sm + OFF_WC2);

    for (int tile = 0; tile < TILES_PER_BLOCK; tile++) {
        int base = t * PTS_PER_BLOCK + tile * TILE;
        if (base >= cnt) break;
        int bi = base + tid;
        bool valid = (bi < cnt);
        int p = g_bucket[f][valid ? bi : (cnt - 1)];

        float px = pos[3*p], py = pos[3*p+1], pz = pos[3*p+2];
        uint4* hrow = (uint4*)(smw + OFF_H + tid*H_STRIDE);

        // ---- L1 half A: h[0..63] -> H words 0..31 ----
        #pragma unroll
        for (int j = 0; j < 64; j += 8) {
            float hv[8];
            #pragma unroll
            for (int u = 0; u < 8; u++) {
                int jj = j + u;
                hv[u] = fmaxf(fmaf(px, sm[OFF_WD1 + 0*HIDDEN + jj],
                              fmaf(py, sm[OFF_WD1 + 1*HIDDEN + jj],
                              fmaf(pz, sm[OFF_WD1 + 2*HIDDEN + jj],
                                   sm[OFF_BD1 + jj]))), 0.f);
            }
            hrow[j >> 3] = make_uint4(packh2(hv[0],hv[1]), packh2(hv[2],hv[3]),
                                      packh2(hv[4],hv[5]), packh2(hv[6],hv[7]));
        }
        __syncwarp();

        // ---- load A-frags half1 (k 0..63) for both m-tiles ----
        unsigned a1[2][4][4];
        #pragma unroll
        for (int mt = 0; mt < 2; mt++) {
            int r0 = wbase + 16*mt + g;
            #pragma unroll
            for (int ks = 0; ks < 4; ks++) {
                int c = 8*ks + tg;
                a1[mt][ks][0] = H32[(r0    )*H_STRIDE + c    ];
                a1[mt][ks][1] = H32[(r0 + 8)*H_STRIDE + c    ];
                a1[mt][ks][2] = H32[(r0    )*H_STRIDE + c + 4];
                a1[mt][ks][3] = H32[(r0 + 8)*H_STRIDE + c + 4];
            }
        }

        // ---- d0 MMA half1: ks 0..3 (global k 0..63) ----
        float cd[2][2][8];   // [mt][nt][cA0..3, cB0..3]
        #pragma unroll
        for (int mt = 0; mt < 2; mt++)
            #pragma unroll
            for (int nt = 0; nt < 2; nt++) {
                int coln = 8*nt + g;
                float* c = cd[mt][nt];
                #pragma unroll
                for (int q = 0; q < 8; q++) c[q] = 0.f;
                #pragma unroll
                for (int ks = 0; ks < 4; ks += 2) {
                    unsigned b00 = WD2w[(8*ks + tg    )*WD2_STRIDE + coln];
                    unsigned b01 = WD2w[(8*ks + tg + 4)*WD2_STRIDE + coln];
                    unsigned b10 = WD2w[(8*(ks+1) + tg    )*WD2_STRIDE + coln];
                    unsigned b11 = WD2w[(8*(ks+1) + tg + 4)*WD2_STRIDE + coln];
                    mma_f16(c[0],c[1],c[2],c[3],
                            a1[mt][ks][0],a1[mt][ks][1],a1[mt][ks][2],a1[mt][ks][3], b00,b01);
                    mma_f16(c[4],c[5],c[6],c[7],
                            a1[mt][ks+1][0],a1[mt][ks+1][1],a1[mt][ks+1][2],a1[mt][ks+1][3], b10,b11);
                }
            }
        __syncwarp();

        // ---- L1 half B: h[64..127] -> overwrite H words 0..31 ----
        #pragma unroll
        for (int j = 64; j < 128; j += 8) {
            float hv[8];
            #pragma unroll
            for (int u = 0; u < 8; u++) {
                int jj = j + u;
                hv[u] = fmaxf(fmaf(px, sm[OFF_WD1 + 0*HIDDEN + jj],
                              fmaf(py, sm[OFF_WD1 + 1*HIDDEN + jj],
                              fmaf(pz, sm[OFF_WD1 + 2*HIDDEN + jj],
                                   sm[OFF_BD1 + jj]))), 0.f);
            }
            hrow[(j - 64) >> 3] = make_uint4(packh2(hv[0],hv[1]), packh2(hv[2],hv[3]),
                                             packh2(hv[4],hv[5]), packh2(hv[6],hv[7]));
        }
        __syncwarp();

        // ---- load A-frags half2, finish d0 MMA (global ks 4..7) ----
        unsigned a2[2][4][4];
        #pragma unroll
        for (int mt = 0; mt < 2; mt++) {
            int r0 = wbase + 16*mt + g;
            #pragma unroll
            for (int ks = 0; ks < 4; ks++) {
                int c = 8*ks + tg;
                a2[mt][ks][0] = H32[(r0    )*H_STRIDE + c    ];
                a2[mt][ks][1] = H32[(r0 + 8)*H_STRIDE + c    ];
                a2[mt][ks][2] = H32[(r0    )*H_STRIDE + c + 4];
                a2[mt][ks][3] = H32[(r0 + 8)*H_STRIDE + c + 4];
            }
        }
        #pragma unroll
        for (int mt = 0; mt < 2; mt++)
            #pragma unroll
            for (int nt = 0; nt < 2; nt++) {
                int coln = 8*nt + g;
                float* c = cd[mt][nt];
                #pragma unroll
                for (int ks = 0; ks < 4; ks += 2) {
                    int gk0 = ks + 4, gk1 = ks + 5;     // global k-tiles for B
                    unsigned b00 = WD2w[(8*gk0 + tg    )*WD2_STRIDE + coln];
                    unsigned b01 = WD2w[(8*gk0 + tg + 4)*WD2_STRIDE + coln];
                    unsigned b10 = WD2w[(8*gk1 + tg    )*WD2_STRIDE + coln];
                    unsigned b11 = WD2w[(8*gk1 + tg + 4)*WD2_STRIDE + coln];
                    mma_f16(c[0],c[1],c[2],c[3],
                            a2[mt][ks][0],a2[mt][ks][1],a2[mt][ks][2],a2[mt][ks][3], b00,b01);
                    mma_f16(c[4],c[5],c[6],c[7],
                            a2[mt][ks+1][0],a2[mt][ks+1][1],a2[mt][ks+1][2],a2[mt][ks+1][3], b10,b11);
                }
            }

        // ---- store d0 into H words 0..15 of own rows (A-frags consumed) ----
        #pragma unroll
        for (int mt = 0; mt < 2; mt++) {
            int r0 = wbase + 16*mt + g;
            #pragma unroll
            for (int nt = 0; nt < 2; nt++) {
                float* c = cd[mt][nt];
                int cb = 8*nt + 2*tg;
                float* rA = sm + OFF_H + (size_t)(r0    )*H_STRIDE + cb;
                float* rB = sm + OFF_H + (size_t)(r0 + 8)*H_STRIDE + cb;
                rA[0] = c[0] + c[4];  rA[1] = c[1] + c[5];
                rB[0] = c[2] + c[6];  rB[1] = c[3] + c[7];
            }
        }
        __syncwarp();

        // ---- readback d0 (own row), density out, build CIN in-place ----
        {
            float d0[16];
            const float4* drow = (const float4*)(sm + OFF_H + (size_t)tid*H_STRIDE);
            #pragma unroll
            for (int q = 0; q < 4; q++) {
                float4 v = drow[q];
                d0[4*q+0] = v.x + sm[OFF_BD2 + 4*q+0];
                d0[4*q+1] = v.y + sm[OFF_BD2 + 4*q+1];
                d0[4*q+2] = v.z + sm[OFF_BD2 + 4*q+2];
                d0[4*q+3] = v.w + sm[OFF_BD2 + 4*q+3];
            }
            if (valid) out[(size_t)4*p] = expf(d0[0]);

            float cv[56];
            cv[0] = dir[3*p]; cv[1] = dir[3*p+1]; cv[2] = dir[3*p+2];
            #pragma unroll
            for (int g2 = 0; g2 < GEO; g2++) cv[3+g2] = d0[1+g2];
            const float4* ap = (const float4*)(app + (size_t)p*APP);
            #pragma unroll
            for (int q = 0; q < APP/4; q++) {
                float4 v = __ldg(&ap[q]);
                cv[18+4*q+0] = v.x; cv[18+4*q+1] = v.y;
                cv[18+4*q+2] = v.z; cv[18+4*q+3] = v.w;
            }
            #pragma unroll
            for (int c = CIN; c < 56; c++) cv[c] = 0.f;
            #pragma unroll
            for (int q = 0; q < 8; q++) {     // words 0..31 (k padded to 64)
                uint4 v;
                v.x = (q < 7) ? packh2(cv[8*q+0], cv[8*q+1]) : 0u;
                v.y = (q < 7) ? packh2(cv[8*q+2], cv[8*q+3]) : 0u;
                v.z = (q < 7) ? packh2(cv[8*q+4], cv[8*q+5]) : 0u;
                v.w = (q < 7) ? packh2(cv[8*q+6], cv[8*q+7]) : 0u;
                hrow[q] = v;
            }
        }
        __syncwarp();

        // ---- color MMA: HC = relu(CIN @ Wc1 + bc1); RGB scalar-fused ----
        unsigned a[2][4][4];
        #pragma unroll
        for (int mt = 0; mt < 2; mt++) {
            int r0 = wbase + 16*mt + g;
            #pragma unroll
            for (int ks = 0; ks < 4; ks++) {
                int c = 8*ks + tg;
                a[mt][ks][0] = H32[(r0    )*H_STRIDE + c    ];
                a[mt][ks][1] = H32[(r0 + 8)*H_STRIDE + c    ];
                a[mt][ks][2] = H32[(r0    )*H_STRIDE + c + 4];
                a[mt][ks][3] = H32[(r0 + 8)*H_STRIDE + c + 4];
            }
        }

        float acc[4][3];
        #pragma unroll
        for (int q = 0; q < 4; q++) { acc[q][0]=0.f; acc[q][1]=0.f; acc[q][2]=0.f; }

        #pragma unroll 2
        for (int nb = 0; nb < 16; nb++) {
            int coln = 8*nb + g;
            unsigned b[4][2];
            #pragma unroll
            for (int ks = 0; ks < 4; ks++) {
                b[ks][0] = W32[(8*ks + tg    )*WC1_STRIDE + coln];
                b[ks][1] = W32[(8*ks + tg + 4)*WC1_STRIDE + coln];
            }
            int j0 = 8*nb + 2*tg;
            float bj0 = sm[OFF_BC1 + j0], bj1 = sm[OFF_BC1 + j0 + 1];
            float4 w0 = WC2v[j0];
            float4 w1 = WC2v[j0 + 1];

            #pragma unroll
            for (int mt = 0; mt < 2; mt++) {
                float cA0=0.f,cA1=0.f,cA2=0.f,cA3=0.f;
                float cB0=0.f,cB1=0.f,cB2=0.f,cB3=0.f;
                mma_f16(cA0,cA1,cA2,cA3, a[mt][0][0],a[mt][0][1],a[mt][0][2],a[mt][0][3], b[0][0],b[0][1]);
                mma_f16(cB0,cB1,cB2,cB3, a[mt][1][0],a[mt][1][1],a[mt][1][2],a[mt][1][3], b[1][0],b[1][1]);
                mma_f16(cA0,cA1,cA2,cA3, a[mt][2][0],a[mt][2][1],a[mt][2][2],a[mt][2][3], b[2][0],b[2][1]);
                mma_f16(cB0,cB1,cB2,cB3, a[mt][3][0],a[mt][3][1],a[mt][3][2],a[mt][3][3], b[3][0],b[3][1]);
                float h00 = fmaxf(cA0 + cB0 + bj0, 0.f);
                float h01 = fmaxf(cA1 + cB1 + bj1, 0.f);
                float h10 = fmaxf(cA2 + cB2 + bj0, 0.f);
                float h11 = fmaxf(cA3 + cB3 + bj1, 0.f);
                int q0 = 2*mt, q1 = 2*mt + 1;
                acc[q0][0] = fmaf(h00, w0.x, fmaf(h01, w1.x, acc[q0][0]));
                acc[q0][1] = fmaf(h00, w0.y, fmaf(h01, w1.y, acc[q0][1]));
                acc[q0][2] = fmaf(h00, w0.z, fmaf(h01, w1.z, acc[q0][2]));
                acc[q1][0] = fmaf(h10, w0.x, fmaf(h11, w1.x, acc[q1][0]));
                acc[q1][1] = fmaf(h10, w0.y, fmaf(h11, w1.y, acc[q1][1]));
                acc[q1][2] = fmaf(h10, w0.z, fmaf(h11, w1.z, acc[q1][2]));
            }
        }

        #pragma unroll
        for (int q = 0; q < 4; q++)
            #pragma unroll
            for (int c = 0; c < 3; c++) {
                float v = acc[q][c];
                v += __shfl_xor_sync(0xffffffffu, v, 1);
                v += __shfl_xor_sync(0xffffffffu, v, 2);
                acc[q][c] = v;
            }

        {
            int row = wbase + g + 8*tg;
            int bi2 = base + row;
            if (bi2 < cnt) {
                int pp = g_bucket[f][bi2];
                float r0 = acc[tg][0] + sm[OFF_BC2 + 0];
                float r1 = acc[tg][1] + sm[OFF_BC2 + 1];
                float r2 = acc[tg][2] + sm[OFF_BC2 + 2];
                out[(size_t)4*pp + 1] = 1.f / (1.f + expf(-r0));
                out[(size_t)4*pp + 2] = 1.f / (1.f + expf(-r1));
                out[(size_t)4*pp + 3] = 1.f / (1.f + expf(-r2));
            }
        }
        __syncwarp();   // protect H reuse next tile
    }
}

// ---------------- launch ----------------
extern "C" void kernel_launch(void* const* d_in, const int* in_sizes, int n_in,
                              void* d_out, int out_size) {
    const float* positions  = (const float*)d_in[0];
    const float* directions = (const float*)d_in[1];
    const float* appearance = (const float*)d_in[2];
    const float* centroids  = (const float*)d_in[3];
    const float* Wd1 = (const float*)d_in[4];
    const float* bd1 = (const float*)d_in[5];
    const float* Wd2 = (const float*)d_in[6];
    const float* bd2 = (const float*)d_in[7];
    const float* Wc1 = (const float*)d_in[8];
    const float* bc1 = (const float*)d_in[9];
    const float* Wc2 = (const float*)d_in[10];
    const float* bc2 = (const float*)d_in[11];
    float* out = (float*)d_out;

    int n = in_sizes[0] / 3;
    if (n > N_MAX) n = N_MAX;
    int tpf = (n + PTS_PER_BLOCK - 1) / PTS_PER_BLOCK;

    cudaFuncSetAttribute(k_field, cudaFuncAttributeMaxDynamicSharedMemorySize,
                         SMEM_BYTES);

    void* cptr = nullptr;
    cudaGetSymbolAddress(&cptr, g_counts);
    cudaMemsetAsync(cptr, 0, N_FIELDS * sizeof(int));

    k_assign<<<(n + 255) / 256, 256>>>(positions, centroids, n);
    k_field<<<N_FIELDS * tpf, TILE, SMEM_BYTES>>>(positions, directions, appearance,
                                                  Wd1, bd1, Wd2, bd2, Wc1, bc1,
                                                  Wc2, bc2, out, tpf);
}